// round 9
// baseline (speedup 1.0000x reference)
#include <cuda_runtime.h>
#include <cuda_fp16.h>
#include <mma.h>
#include <stdint.h>

using namespace nvcuda;

// Problem shape: N=50000 nodes, E=800000 edges, feature dims 128 -> 128 -> 64
#define MAXN 50176
#define MAXE 800000
#define MAXB ((MAXN + 1023) / 1024)

struct __align__(8) half2x2 { __half2 a, b; };

__device__ int g_is64;
__device__ __align__(16) int    g_cnt[MAXN];
__device__ __align__(16) int    g_fill[MAXN];
__device__ __align__(16) int    g_rowptr[MAXN];
__device__ __align__(16) int    g_bsum[MAXB];
__device__ __align__(16) int    g_csr_src[MAXE];
__device__ __align__(16) float  g_dinv[MAXN];
__device__ __align__(16) __half g_h1[MAXN * 128];   // (x @ W1) * dinv[row], fp16
__device__ __align__(16) float  g_acc1[MAXN * 128]; // relu(aggregated layer-1), fp32
__device__ __align__(16) __half g_h2[MAXN * 64];    // (acc1 @ W2) * dinv[row], fp16

__device__ __forceinline__ int edge_at(const void* ei, size_t idx) {
    return g_is64 ? (int)((const long long*)ei)[idx]
                  : ((const int*)ei)[idx];
}

// ---------------------------------------------------------------------------
// Setup: zero cnt/fill (vectorized) + edge dtype detection (int64 LE with
// values < 2^31 => every odd 32-bit word is 0).
// ---------------------------------------------------------------------------
__global__ void setup_kernel(const int* __restrict__ ei_w, int n4) {
    int i = blockIdx.x * blockDim.x + threadIdx.x;
    if (i < n4) {
        reinterpret_cast<int4*>(g_cnt)[i]  = make_int4(0, 0, 0, 0);
        reinterpret_cast<int4*>(g_fill)[i] = make_int4(0, 0, 0, 0);
    }
    if (blockIdx.x == 0 && threadIdx.x == 0) {
        int is64 = 1;
        for (int k = 1; k < 256; k += 2)
            if (ei_w[k] != 0) { is64 = 0; break; }
        g_is64 = is64;
    }
}

__global__ void count_kernel(const void* __restrict__ ei, int E, int N) {
    int e = blockIdx.x * blockDim.x + threadIdx.x;
    if (e < E) {
        int col = edge_at(ei, (size_t)E + e);
        if ((unsigned)col < (unsigned)N) atomicAdd(&g_cnt[col], 1);
    }
}

__global__ void __launch_bounds__(1024) scan_bsum_kernel(int N) {
    __shared__ int wsum[32];
    int b = blockIdx.x, t = threadIdx.x;
    int gid = b * 1024 + t;
    int v = (gid < N) ? g_cnt[gid] : 0;
    for (int o = 16; o > 0; o >>= 1) v += __shfl_down_sync(~0u, v, o);
    if ((t & 31) == 0) wsum[t >> 5] = v;
    __syncthreads();
    if (t < 32) {
        int s = wsum[t];
        for (int o = 16; o > 0; o >>= 1) s += __shfl_down_sync(~0u, s, o);
        if (t == 0) g_bsum[b] = s;
    }
}

// Local scan -> rowptr (+dinv). Each block redundantly scans the 49 block
// sums in shared (cheap) - removes the separate scan_boff launch.
__global__ void __launch_bounds__(1024) scan_local_kernel(int N, int NB) {
    __shared__ int wsum[32];
    __shared__ int boff_s[64];
    int b = blockIdx.x, t = threadIdx.x;

    if (t < 64) boff_s[t] = (t < NB) ? g_bsum[t] : 0;
    __syncthreads();
#pragma unroll
    for (int off = 1; off < 64; off <<= 1) {
        int v = (t < 64 && t >= off) ? boff_s[t - off] : 0;
        __syncthreads();
        if (t < 64) boff_s[t] += v;
        __syncthreads();
    }
    const int boff = (b > 0) ? boff_s[b - 1] : 0;

    int gid = b * 1024 + t;
    int lane = t & 31, w = t >> 5;
    int v = (gid < N) ? g_cnt[gid] : 0;
    int s = v;
    for (int o = 1; o < 32; o <<= 1) {
        int u = __shfl_up_sync(~0u, s, o);
        if (lane >= o) s += u;
    }
    if (lane == 31) wsum[w] = s;
    __syncthreads();
    if (t < 32) {
        int ws = wsum[t];
        for (int o = 1; o < 32; o <<= 1) {
            int u = __shfl_up_sync(~0u, ws, o);
            if (t >= o) ws += u;
        }
        wsum[t] = ws;
    }
    __syncthreads();
    int excl = s - v + ((w > 0) ? wsum[w - 1] : 0) + boff;
    if (gid < N) {
        g_rowptr[gid] = excl;
        g_dinv[gid]   = rsqrtf((float)(v + 1));  // +1 self-loop
    }
}

__global__ void fill_kernel(const void* __restrict__ ei, int E, int N) {
    int e = blockIdx.x * blockDim.x + threadIdx.x;
    if (e < E) {
        int row = edge_at(ei, e);
        int col = edge_at(ei, (size_t)E + e);
        if ((unsigned)row < (unsigned)N && (unsigned)col < (unsigned)N) {
            int pos = g_rowptr[col] + atomicAdd(&g_fill[col], 1);
            g_csr_src[pos] = row;
        }
    }
}

// ---------------------------------------------------------------------------
// Tensor-core GEMM (tf32 wmma m16n16k8):
//   H[row] = half( (X[row] @ W) * dinv[row] )       (pre-scaled fp16 messages)
// Block = 128 threads = 4 warps; warp owns 16 rows x NOUT cols.
// ws[] is reused as the fp32 epilogue staging tile after the mainloop.
// ---------------------------------------------------------------------------
template <int LAYER, int NOUT>
__global__ void __launch_bounds__(128) gemm_tc_kernel(const float* __restrict__ Xin,
                                                      const float* __restrict__ W,
                                                      int N) {
    constexpr int KD = 128, KC = 64;
    __shared__ __align__(16) float ws[KC * NOUT];

    const float* X = (LAYER == 1) ? Xin  : g_acc1;
    __half*      H = (LAYER == 1) ? g_h1 : g_h2;

    const int warp = threadIdx.x >> 5;
    const int lane = threadIdx.x & 31;
    const int row0 = blockIdx.x * 64 + warp * 16;
    const bool active = (row0 + 16 <= N);

    wmma::fragment<wmma::accumulator, 16, 16, 8, float> c[NOUT / 16];
#pragma unroll
    for (int i = 0; i < NOUT / 16; i++) wmma::fill_fragment(c[i], 0.0f);

    for (int kc = 0; kc < KD; kc += KC) {
        __syncthreads();
        for (int i = threadIdx.x; i < KC * NOUT; i += 128)
            ws[i] = wmma::__float_to_tf32(W[(size_t)(kc + i / NOUT) * NOUT + (i % NOUT)]);
        __syncthreads();
        if (active) {
#pragma unroll
            for (int k = 0; k < KC; k += 8) {
                wmma::fragment<wmma::matrix_a, 16, 16, 8, wmma::precision::tf32, wmma::row_major> a;
                wmma::load_matrix_sync(a, X + (size_t)row0 * KD + kc + k, KD);
#pragma unroll
                for (int i = 0; i < a.num_elements; i++)
                    a.x[i] = wmma::__float_to_tf32(a.x[i]);
#pragma unroll
                for (int nt = 0; nt < NOUT / 16; nt++) {
                    wmma::fragment<wmma::matrix_b, 16, 16, 8, wmma::precision::tf32, wmma::row_major> b;
                    wmma::load_matrix_sync(b, ws + k * NOUT + nt * 16, NOUT);
                    wmma::mma_sync(c[nt], a, b, c[nt]);
                }
            }
        }
    }

    __syncthreads();
    if (active) {
        float* tile = ws + warp * 16 * NOUT;
#pragma unroll
        for (int nt = 0; nt < NOUT / 16; nt++)
            wmma::store_matrix_sync(tile + nt * 16, c[nt], NOUT, wmma::mem_row_major);
        __syncwarp();

        constexpr int HV = NOUT / 32;
#pragma unroll 4
        for (int r = 0; r < 16; r++) {
            float d = g_dinv[row0 + r];
            const float* src = tile + r * NOUT + lane * HV;
            __half* dst = H + (size_t)(row0 + r) * NOUT + lane * HV;
            if (HV == 4) {
                float4 v = *reinterpret_cast<const float4*>(src);
                half2x2 p;
                p.a = __floats2half2_rn(v.x * d, v.y * d);
                p.b = __floats2half2_rn(v.z * d, v.w * d);
                *reinterpret_cast<half2x2*>(dst) = p;
            } else {
                float2 v = *reinterpret_cast<const float2*>(src);
                *reinterpret_cast<__half2*>(dst) = __floats2half2_rn(v.x * d, v.y * d);
            }
        }
    } else if (row0 < N) {
        for (int r = row0; r < N; r++) {
            float d = g_dinv[r];
            for (int col = lane; col < NOUT; col += 32) {
                float s = 0.0f;
                for (int k = 0; k < KD; k++)
                    s += X[(size_t)r * KD + k] * W[(size_t)k * NOUT + col];
                H[(size_t)r * NOUT + col] = __float2half(s * d);
            }
        }
    }
}

// ---------------------------------------------------------------------------
// Atomic-free aggregation, one warp per destination node, fp16 messages,
// 8-wide unrolled gathers for MLP.
//   ACC[col] = (relu?)( dinv[col] * ( m[col] + sum m[src] ) + bias )
// ---------------------------------------------------------------------------
template <int F, bool RELU>
__global__ void __launch_bounds__(256) agg_kernel(const float* __restrict__ bias,
                                                  float* __restrict__ OUT2, int N) {
    const __half* HS  = (F == 128) ? g_h1   : g_h2;
    float*        ACC = (F == 128) ? g_acc1 : OUT2;
    constexpr int V = F / 32;  // halves per lane (4 or 2)

    int col  = (blockIdx.x * blockDim.x + threadIdx.x) >> 5;
    int lane = threadIdx.x & 31;
    if (col >= N) return;

    const int   start = g_rowptr[col];
    const int   cnt   = g_cnt[col];
    const float d     = g_dinv[col];

    float v[V];
    {
        const __half* r = HS + (size_t)col * F + lane * V;
        if (V == 4) {
            half2x2 u = *reinterpret_cast<const half2x2*>(r);
            float2 f0 = __half22float2(u.a);
            float2 f1 = __half22float2(u.b);
            v[0] = f0.x; v[1] = f0.y; v[2] = f1.x; v[3] = f1.y;
        } else {
            float2 f = __half22float2(*reinterpret_cast<const __half2*>(r));
            v[0] = f.x; v[1] = f.y;
        }
    }

    int j = 0;
    // 8-wide: prefetch 8 indices, then 8 independent gathers in flight
    for (; j + 8 <= cnt; j += 8) {
        int si[8];
#pragma unroll
        for (int q = 0; q < 8; q++) si[q] = __ldg(&g_csr_src[start + j + q]);
        if (V == 4) {
            half2x2 u[8];
#pragma unroll
            for (int q = 0; q < 8; q++)
                u[q] = *reinterpret_cast<const half2x2*>(HS + (size_t)si[q] * F + lane * 4);
            float s0 = 0, s1 = 0, s2 = 0, s3 = 0;
#pragma unroll
            for (int q = 0; q < 8; q++) {
                float2 fa = __half22float2(u[q].a);
                float2 fb = __half22float2(u[q].b);
                s0 += fa.x; s1 += fa.y; s2 += fb.x; s3 += fb.y;
            }
            v[0] += s0; v[1] += s1; v[2] += s2; v[3] += s3;
        } else {
            __half2 u[8];
#pragma unroll
            for (int q = 0; q < 8; q++)
                u[q] = *reinterpret_cast<const __half2*>(HS + (size_t)si[q] * F + lane * 2);
            float s0 = 0, s1 = 0;
#pragma unroll
            for (int q = 0; q < 8; q++) {
                float2 f = __half22float2(u[q]);
                s0 += f.x; s1 += f.y;
            }
            v[0] += s0; v[1] += s1;
        }
    }
    // 4-wide middle
    for (; j + 4 <= cnt; j += 4) {
        int si[4];
#pragma unroll
        for (int q = 0; q < 4; q++) si[q] = __ldg(&g_csr_src[start + j + q]);
        if (V == 4) {
#pragma unroll
            for (int q = 0; q < 4; q++) {
                half2x2 u = *reinterpret_cast<const half2x2*>(HS + (size_t)si[q] * F + lane * 4);
                float2 fa = __half22float2(u.a), fb = __half22float2(u.b);
                v[0] += fa.x; v[1] += fa.y; v[2] += fb.x; v[3] += fb.y;
            }
        } else {
#pragma unroll
            for (int q = 0; q < 4; q++) {
                float2 f = __half22float2(*reinterpret_cast<const __half2*>(HS + (size_t)si[q] * F + lane * 2));
                v[0] += f.x; v[1] += f.y;
            }
        }
    }
    for (; j < cnt; j++) {
        int src = __ldg(&g_csr_src[start + j]);
        const __half* r = HS + (size_t)src * F + lane * V;
        if (V == 4) {
            half2x2 u = *reinterpret_cast<const half2x2*>(r);
            float2 f0 = __half22float2(u.a), f1 = __half22float2(u.b);
            v[0] += f0.x; v[1] += f0.y; v[2] += f1.x; v[3] += f1.y;
        } else {
            float2 f = __half22float2(*reinterpret_cast<const __half2*>(r));
            v[0] += f.x; v[1] += f.y;
        }
    }

    float* o = ACC + (size_t)col * F + lane * V;
    if (V == 4) {
        float4 b = *reinterpret_cast<const float4*>(bias + lane * 4);
        float4 w;
        w.x = fmaf(v[0], d, b.x); w.y = fmaf(v[1], d, b.y);
        w.z = fmaf(v[2], d, b.z); w.w = fmaf(v[3], d, b.w);
        if (RELU) {
            w.x = fmaxf(w.x, 0.0f); w.y = fmaxf(w.y, 0.0f);
            w.z = fmaxf(w.z, 0.0f); w.w = fmaxf(w.w, 0.0f);
        }
        *reinterpret_cast<float4*>(o) = w;
    } else {
        float2 b = *reinterpret_cast<const float2*>(bias + lane * 2);
        float2 w;
        w.x = fmaf(v[0], d, b.x); w.y = fmaf(v[1], d, b.y);
        if (RELU) { w.x = fmaxf(w.x, 0.0f); w.y = fmaxf(w.y, 0.0f); }
        *reinterpret_cast<float2*>(o) = w;
    }
}

// ---------------------------------------------------------------------------
// Launch (8 kernels)
// ---------------------------------------------------------------------------
extern "C" void kernel_launch(void* const* d_in, const int* in_sizes, int n_in,
                              void* d_out, int out_size) {
    const float* x   = (const float*)d_in[0];
    const void*  ei  = d_in[1];
    const float* W1  = (const float*)d_in[4];
    const float* b1  = (const float*)d_in[5];
    const float* W2  = (const float*)d_in[6];
    const float* b2  = (const float*)d_in[7];
    float*       out = (float*)d_out;

    const int N  = in_sizes[0] / 128;
    const int E  = in_sizes[1] / 2;
    const int NB = (N + 1023) / 1024;
    const int N4 = (N + 3) / 4;

    setup_kernel<<<(N4 + 255) / 256, 256>>>((const int*)ei, N4);
    count_kernel<<<(E + 255) / 256, 256>>>(ei, E, N);
    scan_bsum_kernel<<<NB, 1024>>>(N);
    scan_local_kernel<<<NB, 1024>>>(N, NB);   // boff + rowptr + dinv fused
    fill_kernel<<<(E + 255) / 256, 256>>>(ei, E, N);

    gemm_tc_kernel<1, 128><<<(N + 63) / 64, 128>>>(x, W1, N);
    agg_kernel<128, true><<<(N * 32 + 255) / 256, 256>>>(b1, nullptr, N);
    gemm_tc_kernel<2, 64><<<(N + 63) / 64, 128>>>(nullptr, W2, N);
    agg_kernel<64, false><<<(N * 32 + 255) / 256, 256>>>(b2, out, N);
}

// round 10
// speedup vs baseline: 1.0584x; 1.0584x over previous
#include <cuda_runtime.h>
#include <cuda_fp16.h>
#include <mma.h>
#include <stdint.h>

using namespace nvcuda;

// Problem shape: N=50000 nodes, E=800000 edges, feature dims 128 -> 128 -> 64
#define MAXN 50176
#define MAXE 800000
#define MAXB ((MAXN + 1023) / 1024)

struct __align__(8) half2x2 { __half2 a, b; };

__device__ int g_is64;
__device__ __align__(16) int    g_cnt[MAXN];
__device__ __align__(16) int    g_fill[MAXN];
__device__ __align__(16) int    g_rowptr[MAXN];
__device__ __align__(16) int    g_bsum[MAXB];
__device__ __align__(16) int    g_csr_src[MAXE];
__device__ __align__(16) float  g_dinv[MAXN];
__device__ __align__(16) __half g_h1[MAXN * 128];   // (x @ W1) * dinv[row], fp16
__device__ __align__(16) __half g_acc1[MAXN * 128]; // relu(aggregated layer-1), fp16
__device__ __align__(16) __half g_h2[MAXN * 64];    // (acc1 @ W2) * dinv[row], fp16

__device__ __forceinline__ int edge_at(const void* ei, size_t idx) {
    return g_is64 ? (int)((const long long*)ei)[idx]
                  : ((const int*)ei)[idx];
}

// ---------------------------------------------------------------------------
// Setup: zero cnt/fill + edge dtype detection
// ---------------------------------------------------------------------------
__global__ void setup_kernel(const int* __restrict__ ei_w, int n4) {
    int i = blockIdx.x * blockDim.x + threadIdx.x;
    if (i < n4) {
        reinterpret_cast<int4*>(g_cnt)[i]  = make_int4(0, 0, 0, 0);
        reinterpret_cast<int4*>(g_fill)[i] = make_int4(0, 0, 0, 0);
    }
    if (blockIdx.x == 0 && threadIdx.x == 0) {
        int is64 = 1;
        for (int k = 1; k < 256; k += 2)
            if (ei_w[k] != 0) { is64 = 0; break; }
        g_is64 = is64;
    }
}

__global__ void count_kernel(const void* __restrict__ ei, int E, int N) {
    int e = blockIdx.x * blockDim.x + threadIdx.x;
    if (e < E) {
        int col = edge_at(ei, (size_t)E + e);
        if ((unsigned)col < (unsigned)N) atomicAdd(&g_cnt[col], 1);
    }
}

__global__ void dinv_kernel(int n) {
    int i = blockIdx.x * blockDim.x + threadIdx.x;
    if (i < n) g_dinv[i] = rsqrtf((float)(g_cnt[i] + 1));  // +1 self-loop
}

__global__ void __launch_bounds__(1024) scan_bsum_kernel(int N) {
    __shared__ int wsum[32];
    int b = blockIdx.x, t = threadIdx.x;
    int gid = b * 1024 + t;
    int v = (gid < N) ? g_cnt[gid] : 0;
    for (int o = 16; o > 0; o >>= 1) v += __shfl_down_sync(~0u, v, o);
    if ((t & 31) == 0) wsum[t >> 5] = v;
    __syncthreads();
    if (t < 32) {
        int s = wsum[t];
        for (int o = 16; o > 0; o >>= 1) s += __shfl_down_sync(~0u, s, o);
        if (t == 0) g_bsum[b] = s;
    }
}

// Local scan -> rowptr; block offsets scanned redundantly per block.
__global__ void __launch_bounds__(1024) scan_local_kernel(int N, int NB) {
    __shared__ int wsum[32];
    __shared__ int boff_s[64];
    int b = blockIdx.x, t = threadIdx.x;

    if (t < 64) boff_s[t] = (t < NB) ? g_bsum[t] : 0;
    __syncthreads();
#pragma unroll
    for (int off = 1; off < 64; off <<= 1) {
        int v = (t < 64 && t >= off) ? boff_s[t - off] : 0;
        __syncthreads();
        if (t < 64) boff_s[t] += v;
        __syncthreads();
    }
    const int boff = (b > 0) ? boff_s[b - 1] : 0;

    int gid = b * 1024 + t;
    int lane = t & 31, w = t >> 5;
    int v = (gid < N) ? g_cnt[gid] : 0;
    int s = v;
    for (int o = 1; o < 32; o <<= 1) {
        int u = __shfl_up_sync(~0u, s, o);
        if (lane >= o) s += u;
    }
    if (lane == 31) wsum[w] = s;
    __syncthreads();
    if (t < 32) {
        int ws = wsum[t];
        for (int o = 1; o < 32; o <<= 1) {
            int u = __shfl_up_sync(~0u, ws, o);
            if (t >= o) ws += u;
        }
        wsum[t] = ws;
    }
    __syncthreads();
    int excl = s - v + ((w > 0) ? wsum[w - 1] : 0) + boff;
    if (gid < N) g_rowptr[gid] = excl;
}

__global__ void fill_kernel(const void* __restrict__ ei, int E, int N) {
    int e = blockIdx.x * blockDim.x + threadIdx.x;
    if (e < E) {
        int row = edge_at(ei, e);
        int col = edge_at(ei, (size_t)E + e);
        if ((unsigned)row < (unsigned)N && (unsigned)col < (unsigned)N) {
            int pos = g_rowptr[col] + atomicAdd(&g_fill[col], 1);
            g_csr_src[pos] = row;
        }
    }
}

// ---------------------------------------------------------------------------
// Layer-1 GEMM (tf32 wmma m16n16k8): h1 = half((x @ W1) * dinv[row])
// ---------------------------------------------------------------------------
__global__ void __launch_bounds__(128) gemm1_tc_kernel(const float* __restrict__ X,
                                                       const float* __restrict__ W,
                                                       int N) {
    constexpr int KD = 128, KC = 64, NOUT = 128;
    __shared__ __align__(16) float ws[KC * NOUT];

    const int warp = threadIdx.x >> 5;
    const int lane = threadIdx.x & 31;
    const int row0 = blockIdx.x * 64 + warp * 16;
    const bool active = (row0 + 16 <= N);

    wmma::fragment<wmma::accumulator, 16, 16, 8, float> c[NOUT / 16];
#pragma unroll
    for (int i = 0; i < NOUT / 16; i++) wmma::fill_fragment(c[i], 0.0f);

    for (int kc = 0; kc < KD; kc += KC) {
        __syncthreads();
        for (int i = threadIdx.x; i < KC * NOUT; i += 128)
            ws[i] = wmma::__float_to_tf32(W[(size_t)(kc + i / NOUT) * NOUT + (i % NOUT)]);
        __syncthreads();
        if (active) {
#pragma unroll
            for (int k = 0; k < KC; k += 8) {
                wmma::fragment<wmma::matrix_a, 16, 16, 8, wmma::precision::tf32, wmma::row_major> a;
                wmma::load_matrix_sync(a, X + (size_t)row0 * KD + kc + k, KD);
#pragma unroll
                for (int i = 0; i < a.num_elements; i++)
                    a.x[i] = wmma::__float_to_tf32(a.x[i]);
#pragma unroll
                for (int nt = 0; nt < NOUT / 16; nt++) {
                    wmma::fragment<wmma::matrix_b, 16, 16, 8, wmma::precision::tf32, wmma::row_major> b;
                    wmma::load_matrix_sync(b, ws + k * NOUT + nt * 16, NOUT);
                    wmma::mma_sync(c[nt], a, b, c[nt]);
                }
            }
        }
    }

    __syncthreads();
    if (active) {
        float* tile = ws + warp * 16 * NOUT;
#pragma unroll
        for (int nt = 0; nt < NOUT / 16; nt++)
            wmma::store_matrix_sync(tile + nt * 16, c[nt], NOUT, wmma::mem_row_major);
        __syncwarp();
#pragma unroll 4
        for (int r = 0; r < 16; r++) {
            float d = g_dinv[row0 + r];
            const float* src = tile + r * NOUT + lane * 4;
            float4 v = *reinterpret_cast<const float4*>(src);
            half2x2 p;
            p.a = __floats2half2_rn(v.x * d, v.y * d);
            p.b = __floats2half2_rn(v.z * d, v.w * d);
            *reinterpret_cast<half2x2*>(g_h1 + (size_t)(row0 + r) * NOUT + lane * 4) = p;
        }
    } else if (row0 < N) {
        for (int r = row0; r < N; r++) {
            float d = g_dinv[r];
            for (int col = lane; col < NOUT; col += 32) {
                float s = 0.0f;
                for (int k = 0; k < KD; k++)
                    s += X[(size_t)r * KD + k] * W[(size_t)k * NOUT + col];
                g_h1[(size_t)r * NOUT + col] = __float2half(s * d);
            }
        }
    }
}

// ---------------------------------------------------------------------------
// Layer-2 GEMM (fp16 wmma m16n16k16): h2 = half((acc1 @ W2) * dinv[row])
// W2 (128x64) staged once as fp16 (16KB); fp32 accum; epilogue tile overlays ws.
// ---------------------------------------------------------------------------
__global__ void __launch_bounds__(128) gemm2_tc_kernel(const float* __restrict__ W,
                                                       int N) {
    constexpr int KD = 128, NOUT = 64;
    __shared__ __align__(16) __half wsh[KD * NOUT];  // 16 KB

    const int warp = threadIdx.x >> 5;
    const int lane = threadIdx.x & 31;
    const int row0 = blockIdx.x * 64 + warp * 16;
    const bool active = (row0 + 16 <= N);

    for (int i = threadIdx.x; i < KD * NOUT; i += 128)
        wsh[i] = __float2half(W[i]);
    __syncthreads();

    wmma::fragment<wmma::accumulator, 16, 16, 16, float> c[NOUT / 16];
#pragma unroll
    for (int i = 0; i < NOUT / 16; i++) wmma::fill_fragment(c[i], 0.0f);

    if (active) {
#pragma unroll
        for (int k = 0; k < KD; k += 16) {
            wmma::fragment<wmma::matrix_a, 16, 16, 16, __half, wmma::row_major> a;
            wmma::load_matrix_sync(a, g_acc1 + (size_t)row0 * KD + k, KD);
#pragma unroll
            for (int nt = 0; nt < NOUT / 16; nt++) {
                wmma::fragment<wmma::matrix_b, 16, 16, 16, __half, wmma::row_major> b;
                wmma::load_matrix_sync(b, wsh + k * NOUT + nt * 16, NOUT);
                wmma::mma_sync(c[nt], a, b, c[nt]);
            }
        }
    }

    __syncthreads();
    if (active) {
        float* tile = reinterpret_cast<float*>(wsh) + warp * 16 * NOUT;  // 16KB overlay
#pragma unroll
        for (int nt = 0; nt < NOUT / 16; nt++)
            wmma::store_matrix_sync(tile + nt * 16, c[nt], NOUT, wmma::mem_row_major);
        __syncwarp();
#pragma unroll 4
        for (int r = 0; r < 16; r++) {
            float d = g_dinv[row0 + r];
            float2 v = *reinterpret_cast<const float2*>(tile + r * NOUT + lane * 2);
            *reinterpret_cast<__half2*>(g_h2 + (size_t)(row0 + r) * NOUT + lane * 2) =
                __floats2half2_rn(v.x * d, v.y * d);
        }
    } else if (row0 < N) {
        for (int r = row0; r < N; r++) {
            float d = g_dinv[r];
            for (int col = lane; col < NOUT; col += 32) {
                float s = 0.0f;
                for (int k = 0; k < KD; k++)
                    s += __half2float(g_acc1[(size_t)r * KD + k]) * W[(size_t)k * NOUT + col];
                g_h2[(size_t)r * NOUT + col] = __float2half(s * d);
            }
        }
    }
}

// ---------------------------------------------------------------------------
// Atomic-free aggregation, one warp per destination node, fp16 messages.
// OUT_HALF=1: write relu(result) as fp16 to g_acc1. Else fp32 to OUT2.
// ---------------------------------------------------------------------------
template <int F, bool RELU, bool OUT_HALF>
__global__ void __launch_bounds__(256) agg_kernel(const float* __restrict__ bias,
                                                  float* __restrict__ OUT2, int N) {
    const __half* HS = (F == 128) ? g_h1 : g_h2;
    constexpr int V = F / 32;  // halves per lane (4 or 2)

    int col  = (blockIdx.x * blockDim.x + threadIdx.x) >> 5;
    int lane = threadIdx.x & 31;
    if (col >= N) return;

    const int   start = g_rowptr[col];
    const int   cnt   = g_cnt[col];
    const float d     = g_dinv[col];

    float v[V];
    {
        const __half* r = HS + (size_t)col * F + lane * V;
        if (V == 4) {
            half2x2 u = *reinterpret_cast<const half2x2*>(r);
            float2 f0 = __half22float2(u.a), f1 = __half22float2(u.b);
            v[0] = f0.x; v[1] = f0.y; v[2] = f1.x; v[3] = f1.y;
        } else {
            float2 f = __half22float2(*reinterpret_cast<const __half2*>(r));
            v[0] = f.x; v[1] = f.y;
        }
    }

    int j = 0;
    for (; j + 8 <= cnt; j += 8) {
        int si[8];
#pragma unroll
        for (int q = 0; q < 8; q++) si[q] = __ldg(&g_csr_src[start + j + q]);
        if (V == 4) {
            half2x2 u[8];
#pragma unroll
            for (int q = 0; q < 8; q++)
                u[q] = *reinterpret_cast<const half2x2*>(HS + (size_t)si[q] * F + lane * 4);
            float s0 = 0, s1 = 0, s2 = 0, s3 = 0;
#pragma unroll
            for (int q = 0; q < 8; q++) {
                float2 fa = __half22float2(u[q].a), fb = __half22float2(u[q].b);
                s0 += fa.x; s1 += fa.y; s2 += fb.x; s3 += fb.y;
            }
            v[0] += s0; v[1] += s1; v[2] += s2; v[3] += s3;
        } else {
            __half2 u[8];
#pragma unroll
            for (int q = 0; q < 8; q++)
                u[q] = *reinterpret_cast<const __half2*>(HS + (size_t)si[q] * F + lane * 2);
            float s0 = 0, s1 = 0;
#pragma unroll
            for (int q = 0; q < 8; q++) {
                float2 f = __half22float2(u[q]);
                s0 += f.x; s1 += f.y;
            }
            v[0] += s0; v[1] += s1;
        }
    }
    for (; j < cnt; j++) {
        int src = __ldg(&g_csr_src[start + j]);
        const __half* r = HS + (size_t)src * F + lane * V;
        if (V == 4) {
            half2x2 u = *reinterpret_cast<const half2x2*>(r);
            float2 f0 = __half22float2(u.a), f1 = __half22float2(u.b);
            v[0] += f0.x; v[1] += f0.y; v[2] += f1.x; v[3] += f1.y;
        } else {
            float2 f = __half22float2(*reinterpret_cast<const __half2*>(r));
            v[0] += f.x; v[1] += f.y;
        }
    }

#pragma unroll
    for (int q = 0; q < V; q++) {
        v[q] = fmaf(v[q], d, bias[lane * V + q]);
        if (RELU) v[q] = fmaxf(v[q], 0.0f);
    }

    if (OUT_HALF) {
        __half* o = g_acc1 + (size_t)col * F + lane * V;
        if (V == 4) {
            half2x2 p;
            p.a = __floats2half2_rn(v[0], v[1]);
            p.b = __floats2half2_rn(v[2], v[3]);
            *reinterpret_cast<half2x2*>(o) = p;
        } else {
            *reinterpret_cast<__half2*>(o) = __floats2half2_rn(v[0], v[1]);
        }
    } else {
        float* o = OUT2 + (size_t)col * F + lane * V;
        if (V == 4) {
            float4 w = make_float4(v[0], v[1], v[2], v[3]);
            *reinterpret_cast<float4*>(o) = w;
        } else {
            float2 w = make_float2(v[0], v[1]);
            *reinterpret_cast<float2*>(o) = w;
        }
    }
}

// ---------------------------------------------------------------------------
// Launch (10 kernels; gemm1 is launch #4 -> lands in the ncu capture window)
// ---------------------------------------------------------------------------
extern "C" void kernel_launch(void* const* d_in, const int* in_sizes, int n_in,
                              void* d_out, int out_size) {
    const float* x   = (const float*)d_in[0];
    const void*  ei  = d_in[1];
    const float* W1  = (const float*)d_in[4];
    const float* b1  = (const float*)d_in[5];
    const float* W2  = (const float*)d_in[6];
    const float* b2  = (const float*)d_in[7];
    float*       out = (float*)d_out;

    const int N  = in_sizes[0] / 128;
    const int E  = in_sizes[1] / 2;
    const int NB = (N + 1023) / 1024;
    const int N4 = (N + 3) / 4;

    setup_kernel<<<(N4 + 255) / 256, 256>>>((const int*)ei, N4);   // 1
    count_kernel<<<(E + 255) / 256, 256>>>(ei, E, N);              // 2
    dinv_kernel<<<(N + 255) / 256, 256>>>(N);                      // 3
    gemm1_tc_kernel<<<(N + 63) / 64, 128>>>(x, W1, N);             // 4 <- profiled
    scan_bsum_kernel<<<NB, 1024>>>(N);                             // 5
    scan_local_kernel<<<NB, 1024>>>(N, NB);                        // 6
    fill_kernel<<<(E + 255) / 256, 256>>>(ei, E, N);               // 7
    agg_kernel<128, true, true><<<(N * 32 + 255) / 256, 256>>>(b1, nullptr, N);  // 8
    gemm2_tc_kernel<<<(N + 63) / 64, 128>>>(W2, N);                // 9
    agg_kernel<64, false, false><<<(N * 32 + 255) / 256, 256>>>(b2, out, N);     // 10
}

// round 11
// speedup vs baseline: 1.4063x; 1.3287x over previous
#include <cuda_runtime.h>
#include <cuda_fp16.h>
#include <mma.h>
#include <stdint.h>

using namespace nvcuda;

// Problem shape: N=50000 nodes, E=800000 edges, feature dims 128 -> 128 -> 64
#define MAXN 50176
#define MAXE 800000
#define MAXB ((MAXN + 1023) / 1024)

struct __align__(8) half2x2 { __half2 a, b; };

__device__ int g_is64;
__device__ __align__(16) int    g_cnt[MAXN];
__device__ __align__(16) int    g_fill[MAXN];
__device__ __align__(16) int    g_rowptr[MAXN];
__device__ __align__(16) int    g_bsum[MAXB];
__device__ __align__(16) int    g_csr_src[MAXE];
__device__ __align__(16) float  g_dinv[MAXN];
__device__ __align__(16) __half g_x16[MAXN * 128];  // x converted to fp16
__device__ __align__(16) __half g_h1[MAXN * 128];   // (x @ W1) * dinv[row], fp16
__device__ __align__(16) __half g_acc1[MAXN * 128]; // relu(aggregated layer-1), fp16
__device__ __align__(16) __half g_h2[MAXN * 64];    // (acc1 @ W2) * dinv[row], fp16

__device__ __forceinline__ int edge_at(const void* ei, size_t idx) {
    return g_is64 ? (int)((const long long*)ei)[idx]
                  : ((const int*)ei)[idx];
}

// ---------------------------------------------------------------------------
// Setup: zero cnt/fill, convert x -> fp16 (8 floats/thread), detect edge dtype
// ---------------------------------------------------------------------------
__global__ void setup_kernel(const float* __restrict__ x,
                             const int* __restrict__ ei_w, int n4, int nx8) {
    int i = blockIdx.x * blockDim.x + threadIdx.x;
    if (i < n4) {
        reinterpret_cast<int4*>(g_cnt)[i]  = make_int4(0, 0, 0, 0);
        reinterpret_cast<int4*>(g_fill)[i] = make_int4(0, 0, 0, 0);
    }
    if (i < nx8) {
        float4 a = reinterpret_cast<const float4*>(x)[i * 2 + 0];
        float4 b = reinterpret_cast<const float4*>(x)[i * 2 + 1];
        half2x2 p0, p1;
        p0.a = __floats2half2_rn(a.x, a.y); p0.b = __floats2half2_rn(a.z, a.w);
        p1.a = __floats2half2_rn(b.x, b.y); p1.b = __floats2half2_rn(b.z, b.w);
        reinterpret_cast<half2x2*>(g_x16)[i * 2 + 0] = p0;
        reinterpret_cast<half2x2*>(g_x16)[i * 2 + 1] = p1;
    }
    if (blockIdx.x == 0 && threadIdx.x == 0) {
        int is64 = 1;
        for (int k = 1; k < 256; k += 2)
            if (ei_w[k] != 0) { is64 = 0; break; }
        g_is64 = is64;
    }
}

__global__ void count_kernel(const void* __restrict__ ei, int E, int N) {
    int e = blockIdx.x * blockDim.x + threadIdx.x;
    if (e < E) {
        int col = edge_at(ei, (size_t)E + e);
        if ((unsigned)col < (unsigned)N) atomicAdd(&g_cnt[col], 1);
    }
}

__global__ void dinv_kernel(int n) {
    int i = blockIdx.x * blockDim.x + threadIdx.x;
    if (i < n) g_dinv[i] = rsqrtf((float)(g_cnt[i] + 1));  // +1 self-loop
}

__global__ void __launch_bounds__(1024) scan_bsum_kernel(int N) {
    __shared__ int wsum[32];
    int b = blockIdx.x, t = threadIdx.x;
    int gid = b * 1024 + t;
    int v = (gid < N) ? g_cnt[gid] : 0;
    for (int o = 16; o > 0; o >>= 1) v += __shfl_down_sync(~0u, v, o);
    if ((t & 31) == 0) wsum[t >> 5] = v;
    __syncthreads();
    if (t < 32) {
        int s = wsum[t];
        for (int o = 16; o > 0; o >>= 1) s += __shfl_down_sync(~0u, s, o);
        if (t == 0) g_bsum[b] = s;
    }
}

__global__ void __launch_bounds__(1024) scan_local_kernel(int N, int NB) {
    __shared__ int wsum[32];
    __shared__ int boff_s[64];
    int b = blockIdx.x, t = threadIdx.x;

    if (t < 64) boff_s[t] = (t < NB) ? g_bsum[t] : 0;
    __syncthreads();
#pragma unroll
    for (int off = 1; off < 64; off <<= 1) {
        int v = (t < 64 && t >= off) ? boff_s[t - off] : 0;
        __syncthreads();
        if (t < 64) boff_s[t] += v;
        __syncthreads();
    }
    const int boff = (b > 0) ? boff_s[b - 1] : 0;

    int gid = b * 1024 + t;
    int lane = t & 31, w = t >> 5;
    int v = (gid < N) ? g_cnt[gid] : 0;
    int s = v;
    for (int o = 1; o < 32; o <<= 1) {
        int u = __shfl_up_sync(~0u, s, o);
        if (lane >= o) s += u;
    }
    if (lane == 31) wsum[w] = s;
    __syncthreads();
    if (t < 32) {
        int ws = wsum[t];
        for (int o = 1; o < 32; o <<= 1) {
            int u = __shfl_up_sync(~0u, ws, o);
            if (t >= o) ws += u;
        }
        wsum[t] = ws;
    }
    __syncthreads();
    int excl = s - v + ((w > 0) ? wsum[w - 1] : 0) + boff;
    if (gid < N) g_rowptr[gid] = excl;
}

__global__ void fill_kernel(const void* __restrict__ ei, int E, int N) {
    int e = blockIdx.x * blockDim.x + threadIdx.x;
    if (e < E) {
        int row = edge_at(ei, e);
        int col = edge_at(ei, (size_t)E + e);
        if ((unsigned)row < (unsigned)N && (unsigned)col < (unsigned)N) {
            int pos = g_rowptr[col] + atomicAdd(&g_fill[col], 1);
            g_csr_src[pos] = row;
        }
    }
}

// ---------------------------------------------------------------------------
// Layer-1 GEMM (fp16 wmma m16n16k16): h1 = half((x16 @ W1) * dinv[row])
// W1 staged once as fp16, padded (128 x 136) for conflict-free B loads.
// A fragments load directly from g_x16 (fp16, 256B rows). fp32 accumulate.
// Epilogue overlays the W tile as an fp32 staging buffer.
// ---------------------------------------------------------------------------
__global__ void __launch_bounds__(128) gemm1_tc_kernel(const float* __restrict__ W,
                                                       int N) {
    constexpr int KD = 128, NOUT = 128, LDW = NOUT + 8;
    __shared__ __align__(16) __half wsh[KD * LDW];  // 34816 B

    const int warp = threadIdx.x >> 5;
    const int lane = threadIdx.x & 31;
    const int row0 = blockIdx.x * 64 + warp * 16;
    const bool active = (row0 + 16 <= N);

    for (int i = threadIdx.x; i < KD * NOUT; i += 128)
        wsh[(i / NOUT) * LDW + (i % NOUT)] = __float2half(W[i]);
    __syncthreads();

    wmma::fragment<wmma::accumulator, 16, 16, 16, float> c[NOUT / 16];
#pragma unroll
    for (int i = 0; i < NOUT / 16; i++) wmma::fill_fragment(c[i], 0.0f);

    if (active) {
#pragma unroll
        for (int k = 0; k < KD; k += 16) {
            wmma::fragment<wmma::matrix_a, 16, 16, 16, __half, wmma::row_major> a;
            wmma::load_matrix_sync(a, g_x16 + (size_t)row0 * KD + k, KD);
#pragma unroll
            for (int nt = 0; nt < NOUT / 16; nt++) {
                wmma::fragment<wmma::matrix_b, 16, 16, 16, __half, wmma::row_major> b;
                wmma::load_matrix_sync(b, wsh + k * LDW + nt * 16, LDW);
                wmma::mma_sync(c[nt], a, b, c[nt]);
            }
        }
    }

    __syncthreads();  // done reading wsh; reuse as fp32 epilogue tile
    if (active) {
        float* tile = reinterpret_cast<float*>(wsh) + warp * 16 * NOUT;  // 4*16*128*4 = 32KB <= 34.8KB
#pragma unroll
        for (int nt = 0; nt < NOUT / 16; nt++)
            wmma::store_matrix_sync(tile + nt * 16, c[nt], NOUT, wmma::mem_row_major);
        __syncwarp();
#pragma unroll 4
        for (int r = 0; r < 16; r++) {
            float d = g_dinv[row0 + r];
            float4 v = *reinterpret_cast<const float4*>(tile + r * NOUT + lane * 4);
            half2x2 p;
            p.a = __floats2half2_rn(v.x * d, v.y * d);
            p.b = __floats2half2_rn(v.z * d, v.w * d);
            *reinterpret_cast<half2x2*>(g_h1 + (size_t)(row0 + r) * NOUT + lane * 4) = p;
        }
    } else if (row0 < N) {
        for (int r = row0; r < N; r++) {
            float d = g_dinv[r];
            for (int col = lane; col < NOUT; col += 32) {
                float s = 0.0f;
                for (int k = 0; k < KD; k++)
                    s += __half2float(g_x16[(size_t)r * KD + k]) *
                         __half2float(wsh[k * LDW + col]);
                g_h1[(size_t)r * NOUT + col] = __float2half(s * d);
            }
        }
    }
}

// ---------------------------------------------------------------------------
// Layer-2 GEMM (fp16 wmma m16n16k16): h2 = half((acc1 @ W2) * dinv[row])
// ---------------------------------------------------------------------------
__global__ void __launch_bounds__(128) gemm2_tc_kernel(const float* __restrict__ W,
                                                       int N) {
    constexpr int KD = 128, NOUT = 64, LDW = NOUT + 8;
    __shared__ __align__(16) __half wsh[KD * LDW];  // 18432 B

    const int warp = threadIdx.x >> 5;
    const int lane = threadIdx.x & 31;
    const int row0 = blockIdx.x * 64 + warp * 16;
    const bool active = (row0 + 16 <= N);

    for (int i = threadIdx.x; i < KD * NOUT; i += 128)
        wsh[(i / NOUT) * LDW + (i % NOUT)] = __float2half(W[i]);
    __syncthreads();

    wmma::fragment<wmma::accumulator, 16, 16, 16, float> c[NOUT / 16];
#pragma unroll
    for (int i = 0; i < NOUT / 16; i++) wmma::fill_fragment(c[i], 0.0f);

    if (active) {
#pragma unroll
        for (int k = 0; k < KD; k += 16) {
            wmma::fragment<wmma::matrix_a, 16, 16, 16, __half, wmma::row_major> a;
            wmma::load_matrix_sync(a, g_acc1 + (size_t)row0 * KD + k, KD);
#pragma unroll
            for (int nt = 0; nt < NOUT / 16; nt++) {
                wmma::fragment<wmma::matrix_b, 16, 16, 16, __half, wmma::row_major> b;
                wmma::load_matrix_sync(b, wsh + k * LDW + nt * 16, LDW);
                wmma::mma_sync(c[nt], a, b, c[nt]);
            }
        }
    }

    __syncthreads();
    if (active) {
        float* tile = reinterpret_cast<float*>(wsh) + warp * 16 * NOUT;  // 16KB <= 18.4KB
#pragma unroll
        for (int nt = 0; nt < NOUT / 16; nt++)
            wmma::store_matrix_sync(tile + nt * 16, c[nt], NOUT, wmma::mem_row_major);
        __syncwarp();
#pragma unroll 4
        for (int r = 0; r < 16; r++) {
            float d = g_dinv[row0 + r];
            float2 v = *reinterpret_cast<const float2*>(tile + r * NOUT + lane * 2);
            *reinterpret_cast<__half2*>(g_h2 + (size_t)(row0 + r) * NOUT + lane * 2) =
                __floats2half2_rn(v.x * d, v.y * d);
        }
    } else if (row0 < N) {
        for (int r = row0; r < N; r++) {
            float d = g_dinv[r];
            for (int col = lane; col < NOUT; col += 32) {
                float s = 0.0f;
                for (int k = 0; k < KD; k++)
                    s += __half2float(g_acc1[(size_t)r * KD + k]) *
                         __half2float(wsh[k * LDW + col]);
                g_h2[(size_t)r * NOUT + col] = __float2half(s * d);
            }
        }
    }
}

// ---------------------------------------------------------------------------
// Atomic-free aggregation, one warp per destination node, fp16 messages.
// ---------------------------------------------------------------------------
template <int F, bool RELU, bool OUT_HALF>
__global__ void __launch_bounds__(256) agg_kernel(const float* __restrict__ bias,
                                                  float* __restrict__ OUT2, int N) {
    const __half* HS = (F == 128) ? g_h1 : g_h2;
    constexpr int V = F / 32;

    int col  = (blockIdx.x * blockDim.x + threadIdx.x) >> 5;
    int lane = threadIdx.x & 31;
    if (col >= N) return;

    const int   start = g_rowptr[col];
    const int   cnt   = g_cnt[col];
    const float d     = g_dinv[col];

    float v[V];
    {
        const __half* r = HS + (size_t)col * F + lane * V;
        if (V == 4) {
            half2x2 u = *reinterpret_cast<const half2x2*>(r);
            float2 f0 = __half22float2(u.a), f1 = __half22float2(u.b);
            v[0] = f0.x; v[1] = f0.y; v[2] = f1.x; v[3] = f1.y;
        } else {
            float2 f = __half22float2(*reinterpret_cast<const __half2*>(r));
            v[0] = f.x; v[1] = f.y;
        }
    }

    int j = 0;
    for (; j + 8 <= cnt; j += 8) {
        int si[8];
#pragma unroll
        for (int q = 0; q < 8; q++) si[q] = __ldg(&g_csr_src[start + j + q]);
        if (V == 4) {
            half2x2 u[8];
#pragma unroll
            for (int q = 0; q < 8; q++)
                u[q] = *reinterpret_cast<const half2x2*>(HS + (size_t)si[q] * F + lane * 4);
            float s0 = 0, s1 = 0, s2 = 0, s3 = 0;
#pragma unroll
            for (int q = 0; q < 8; q++) {
                float2 fa = __half22float2(u[q].a), fb = __half22float2(u[q].b);
                s0 += fa.x; s1 += fa.y; s2 += fb.x; s3 += fb.y;
            }
            v[0] += s0; v[1] += s1; v[2] += s2; v[3] += s3;
        } else {
            __half2 u[8];
#pragma unroll
            for (int q = 0; q < 8; q++)
                u[q] = *reinterpret_cast<const __half2*>(HS + (size_t)si[q] * F + lane * 2);
            float s0 = 0, s1 = 0;
#pragma unroll
            for (int q = 0; q < 8; q++) {
                float2 f = __half22float2(u[q]);
                s0 += f.x; s1 += f.y;
            }
            v[0] += s0; v[1] += s1;
        }
    }
    for (; j < cnt; j++) {
        int src = __ldg(&g_csr_src[start + j]);
        const __half* r = HS + (size_t)src * F + lane * V;
        if (V == 4) {
            half2x2 u = *reinterpret_cast<const half2x2*>(r);
            float2 f0 = __half22float2(u.a), f1 = __half22float2(u.b);
            v[0] += f0.x; v[1] += f0.y; v[2] += f1.x; v[3] += f1.y;
        } else {
            float2 f = __half22float2(*reinterpret_cast<const __half2*>(r));
            v[0] += f.x; v[1] += f.y;
        }
    }

#pragma unroll
    for (int q = 0; q < V; q++) {
        v[q] = fmaf(v[q], d, bias[lane * V + q]);
        if (RELU) v[q] = fmaxf(v[q], 0.0f);
    }

    if (OUT_HALF) {
        __half* o = g_acc1 + (size_t)col * F + lane * V;
        if (V == 4) {
            half2x2 p;
            p.a = __floats2half2_rn(v[0], v[1]);
            p.b = __floats2half2_rn(v[2], v[3]);
            *reinterpret_cast<half2x2*>(o) = p;
        } else {
            *reinterpret_cast<__half2*>(o) = __floats2half2_rn(v[0], v[1]);
        }
    } else {
        float* o = OUT2 + (size_t)col * F + lane * V;
        if (V == 4) {
            *reinterpret_cast<float4*>(o) = make_float4(v[0], v[1], v[2], v[3]);
        } else {
            *reinterpret_cast<float2*>(o) = make_float2(v[0], v[1]);
        }
    }
}

// ---------------------------------------------------------------------------
// Launch (10 kernels; gemm1 stays launch #4 -> profiled)
// ---------------------------------------------------------------------------
extern "C" void kernel_launch(void* const* d_in, const int* in_sizes, int n_in,
                              void* d_out, int out_size) {
    const float* x   = (const float*)d_in[0];
    const void*  ei  = d_in[1];
    const float* W1  = (const float*)d_in[4];
    const float* b1  = (const float*)d_in[5];
    const float* W2  = (const float*)d_in[6];
    const float* b2  = (const float*)d_in[7];
    float*       out = (float*)d_out;

    const int N   = in_sizes[0] / 128;
    const int E   = in_sizes[1] / 2;
    const int NB  = (N + 1023) / 1024;
    const int N4  = (N + 3) / 4;
    const int NX8 = (N * 128) / 8;

    setup_kernel<<<(NX8 + 255) / 256, 256>>>(x, (const int*)ei, N4, NX8);  // 1
    count_kernel<<<(E + 255) / 256, 256>>>(ei, E, N);                      // 2
    dinv_kernel<<<(N + 255) / 256, 256>>>(N);                              // 3
    gemm1_tc_kernel<<<(N + 63) / 64, 128>>>(W1, N);                        // 4 <- profiled
    scan_bsum_kernel<<<NB, 1024>>>(N);                                     // 5
    scan_local_kernel<<<NB, 1024>>>(N, NB);                                // 6
    fill_kernel<<<(E + 255) / 256, 256>>>(ei, E, N);                       // 7
    agg_kernel<128, true, true><<<(N * 32 + 255) / 256, 256>>>(b1, nullptr, N);  // 8
    gemm2_tc_kernel<<<(N + 63) / 64, 128>>>(W2, N);                        // 9
    agg_kernel<64, false, false><<<(N * 32 + 255) / 256, 256>>>(b2, out, N);     // 10
}

// round 12
// speedup vs baseline: 1.5293x; 1.0874x over previous
#include <cuda_runtime.h>
#include <cuda_fp16.h>
#include <mma.h>
#include <stdint.h>

using namespace nvcuda;

// Problem shape: N=50000 nodes, E=800000 edges, feature dims 128 -> 128 -> 64
#define MAXN 50176
#define MAXE 800000
#define MAXB ((MAXN + 1023) / 1024)

struct __align__(8) half2x2 { __half2 a, b; };

__device__ int g_is64;
__device__ __align__(16) int    g_cnt[MAXN];
__device__ __align__(16) int    g_fill[MAXN];
__device__ __align__(16) int    g_rowptr[MAXN];
__device__ __align__(16) int    g_bsum[MAXB];
__device__ __align__(16) int    g_csr_src[MAXE];
__device__ __align__(16) float  g_dinv[MAXN];
__device__ __align__(16) __half g_x16[MAXN * 128];  // x converted to fp16
__device__ __align__(16) __half g_h1[MAXN * 128];   // (x @ W1) * dinv[row], fp16
__device__ __align__(16) __half g_acc1[MAXN * 128]; // relu(aggregated layer-1), fp16
__device__ __align__(16) __half g_h2[MAXN * 64];    // (acc1 @ W2) * dinv[row], fp16

__device__ __forceinline__ int edge_at(const void* ei, size_t idx) {
    return g_is64 ? (int)((const long long*)ei)[idx]
                  : ((const int*)ei)[idx];
}

// ---------------------------------------------------------------------------
// Setup: zero cnt/fill, convert x -> fp16, detect edge dtype
// ---------------------------------------------------------------------------
__global__ void setup_kernel(const float* __restrict__ x,
                             const int* __restrict__ ei_w, int n4, int nx8) {
    int i = blockIdx.x * blockDim.x + threadIdx.x;
    if (i < n4) {
        reinterpret_cast<int4*>(g_cnt)[i]  = make_int4(0, 0, 0, 0);
        reinterpret_cast<int4*>(g_fill)[i] = make_int4(0, 0, 0, 0);
    }
    if (i < nx8) {
        float4 a = reinterpret_cast<const float4*>(x)[i * 2 + 0];
        float4 b = reinterpret_cast<const float4*>(x)[i * 2 + 1];
        half2x2 p0, p1;
        p0.a = __floats2half2_rn(a.x, a.y); p0.b = __floats2half2_rn(a.z, a.w);
        p1.a = __floats2half2_rn(b.x, b.y); p1.b = __floats2half2_rn(b.z, b.w);
        reinterpret_cast<half2x2*>(g_x16)[i * 2 + 0] = p0;
        reinterpret_cast<half2x2*>(g_x16)[i * 2 + 1] = p1;
    }
    if (blockIdx.x == 0 && threadIdx.x == 0) {
        int is64 = 1;
        for (int k = 1; k < 256; k += 2)
            if (ei_w[k] != 0) { is64 = 0; break; }
        g_is64 = is64;
    }
}

__global__ void count_kernel(const void* __restrict__ ei, int E, int N) {
    int e = blockIdx.x * blockDim.x + threadIdx.x;
    if (e < E) {
        int col = edge_at(ei, (size_t)E + e);
        if ((unsigned)col < (unsigned)N) atomicAdd(&g_cnt[col], 1);
    }
}

__global__ void dinv_kernel(int n) {
    int i = blockIdx.x * blockDim.x + threadIdx.x;
    if (i < n) g_dinv[i] = rsqrtf((float)(g_cnt[i] + 1));  // +1 self-loop
}

__global__ void __launch_bounds__(1024) scan_bsum_kernel(int N) {
    __shared__ int wsum[32];
    int b = blockIdx.x, t = threadIdx.x;
    int gid = b * 1024 + t;
    int v = (gid < N) ? g_cnt[gid] : 0;
    for (int o = 16; o > 0; o >>= 1) v += __shfl_down_sync(~0u, v, o);
    if ((t & 31) == 0) wsum[t >> 5] = v;
    __syncthreads();
    if (t < 32) {
        int s = wsum[t];
        for (int o = 16; o > 0; o >>= 1) s += __shfl_down_sync(~0u, s, o);
        if (t == 0) g_bsum[b] = s;
    }
}

__global__ void __launch_bounds__(1024) scan_local_kernel(int N, int NB) {
    __shared__ int wsum[32];
    __shared__ int boff_s[64];
    int b = blockIdx.x, t = threadIdx.x;

    if (t < 64) boff_s[t] = (t < NB) ? g_bsum[t] : 0;
    __syncthreads();
#pragma unroll
    for (int off = 1; off < 64; off <<= 1) {
        int v = (t < 64 && t >= off) ? boff_s[t - off] : 0;
        __syncthreads();
        if (t < 64) boff_s[t] += v;
        __syncthreads();
    }
    const int boff = (b > 0) ? boff_s[b - 1] : 0;

    int gid = b * 1024 + t;
    int lane = t & 31, w = t >> 5;
    int v = (gid < N) ? g_cnt[gid] : 0;
    int s = v;
    for (int o = 1; o < 32; o <<= 1) {
        int u = __shfl_up_sync(~0u, s, o);
        if (lane >= o) s += u;
    }
    if (lane == 31) wsum[w] = s;
    __syncthreads();
    if (t < 32) {
        int ws = wsum[t];
        for (int o = 1; o < 32; o <<= 1) {
            int u = __shfl_up_sync(~0u, ws, o);
            if (t >= o) ws += u;
        }
        wsum[t] = ws;
    }
    __syncthreads();
    int excl = s - v + ((w > 0) ? wsum[w - 1] : 0) + boff;
    if (gid < N) g_rowptr[gid] = excl;
}

__global__ void fill_kernel(const void* __restrict__ ei, int E, int N) {
    int e = blockIdx.x * blockDim.x + threadIdx.x;
    if (e < E) {
        int row = edge_at(ei, e);
        int col = edge_at(ei, (size_t)E + e);
        if ((unsigned)row < (unsigned)N && (unsigned)col < (unsigned)N) {
            int pos = g_rowptr[col] + atomicAdd(&g_fill[col], 1);
            g_csr_src[pos] = row;
        }
    }
}

// ---------------------------------------------------------------------------
// Layer-1 GEMM (fp16 wmma m16n16k16): h1 = half((x16 @ W1) * dinv[row])
// 256 threads, 128 rows/block. W (128x128) and A (128x128) both staged in
// padded smem (coalesced loads, LDSM fragment reads). Epilogue reuses the
// A tile as fp32 staging in two 4-warp phases.
// ---------------------------------------------------------------------------
__global__ void __launch_bounds__(256, 3) gemm1_tc_kernel(const float* __restrict__ W,
                                                          int N) {
    constexpr int KD = 128, NOUT = 128, LDW = 136, ROWS = 128;
    __shared__ __align__(16) __half wsh[KD * LDW];    // 34816 B
    __shared__ __align__(16) __half ash[ROWS * LDW];  // 34816 B

    const int warp = threadIdx.x >> 5;
    const int lane = threadIdx.x & 31;
    const int rowB = blockIdx.x * ROWS;

    // Stage W: float4 coalesced read, 4 halves per store
    for (int i = threadIdx.x; i < KD * (NOUT / 4); i += 256) {
        int k = i >> 5, n = (i & 31) * 4;
        float4 w4 = *reinterpret_cast<const float4*>(W + (size_t)k * NOUT + n);
        half2x2* dst = reinterpret_cast<half2x2*>(&wsh[k * LDW + n]);
        half2x2 p; p.a = __floats2half2_rn(w4.x, w4.y); p.b = __floats2half2_rn(w4.z, w4.w);
        *dst = p;
    }
    // Stage A: uint4 coalesced (8 halves), zero-fill rows >= N
    for (int i = threadIdx.x; i < ROWS * (KD / 8); i += 256) {
        int r = i >> 4, c = (i & 15) * 8;
        uint4 u = (rowB + r < N)
            ? *reinterpret_cast<const uint4*>(g_x16 + (size_t)(rowB + r) * KD + c)
            : make_uint4(0, 0, 0, 0);
        *reinterpret_cast<uint4*>(&ash[r * LDW + c]) = u;
    }
    __syncthreads();

    wmma::fragment<wmma::accumulator, 16, 16, 16, float> c[NOUT / 16];
#pragma unroll
    for (int i = 0; i < NOUT / 16; i++) wmma::fill_fragment(c[i], 0.0f);

    const int r0 = warp * 16;  // warp's row offset within the block tile
#pragma unroll
    for (int k = 0; k < KD; k += 16) {
        wmma::fragment<wmma::matrix_a, 16, 16, 16, __half, wmma::row_major> a;
        wmma::load_matrix_sync(a, ash + r0 * LDW + k, LDW);
#pragma unroll
        for (int nt = 0; nt < NOUT / 16; nt++) {
            wmma::fragment<wmma::matrix_b, 16, 16, 16, __half, wmma::row_major> b;
            wmma::load_matrix_sync(b, wsh + k * LDW + nt * 16, LDW);
            wmma::mma_sync(c[nt], a, b, c[nt]);
        }
    }

    // Epilogue: two phases of 4 warps, fp32 tile overlays ash (32KB <= 34.8KB)
#pragma unroll
    for (int phase = 0; phase < 2; phase++) {
        __syncthreads();
        if ((warp >> 2) == phase) {
            float* tile = reinterpret_cast<float*>(ash) + (warp & 3) * 16 * NOUT;
#pragma unroll
            for (int nt = 0; nt < NOUT / 16; nt++)
                wmma::store_matrix_sync(tile + nt * 16, c[nt], NOUT, wmma::mem_row_major);
            __syncwarp();
#pragma unroll 4
            for (int r = 0; r < 16; r++) {
                int grow = rowB + r0 + r;
                if (grow < N) {
                    float d = g_dinv[grow];
                    float4 v = *reinterpret_cast<const float4*>(tile + r * NOUT + lane * 4);
                    half2x2 p;
                    p.a = __floats2half2_rn(v.x * d, v.y * d);
                    p.b = __floats2half2_rn(v.z * d, v.w * d);
                    *reinterpret_cast<half2x2*>(g_h1 + (size_t)grow * NOUT + lane * 4) = p;
                }
            }
        }
    }
}

// ---------------------------------------------------------------------------
// Layer-2 GEMM (fp16 wmma m16n16k16): h2 = half((acc1 @ W2) * dinv[row])
// Same structure; single-phase epilogue (8 warps x 4KB = 32KB <= ash).
// ---------------------------------------------------------------------------
__global__ void __launch_bounds__(256, 3) gemm2_tc_kernel(const float* __restrict__ W,
                                                          int N) {
    constexpr int KD = 128, NOUT = 64, LDW = 72, LDA = 136, ROWS = 128;
    __shared__ __align__(16) __half wsh[KD * LDW];    // 18432 B
    __shared__ __align__(16) __half ash[ROWS * LDA];  // 34816 B

    const int warp = threadIdx.x >> 5;
    const int lane = threadIdx.x & 31;
    const int rowB = blockIdx.x * ROWS;

    for (int i = threadIdx.x; i < KD * (NOUT / 4); i += 256) {
        int k = i >> 4, n = (i & 15) * 4;
        float4 w4 = *reinterpret_cast<const float4*>(W + (size_t)k * NOUT + n);
        half2x2 p; p.a = __floats2half2_rn(w4.x, w4.y); p.b = __floats2half2_rn(w4.z, w4.w);
        *reinterpret_cast<half2x2*>(&wsh[k * LDW + n]) = p;
    }
    for (int i = threadIdx.x; i < ROWS * (KD / 8); i += 256) {
        int r = i >> 4, c = (i & 15) * 8;
        uint4 u = (rowB + r < N)
            ? *reinterpret_cast<const uint4*>(g_acc1 + (size_t)(rowB + r) * KD + c)
            : make_uint4(0, 0, 0, 0);
        *reinterpret_cast<uint4*>(&ash[r * LDA + c]) = u;
    }
    __syncthreads();

    wmma::fragment<wmma::accumulator, 16, 16, 16, float> c[NOUT / 16];
#pragma unroll
    for (int i = 0; i < NOUT / 16; i++) wmma::fill_fragment(c[i], 0.0f);

    const int r0 = warp * 16;
#pragma unroll
    for (int k = 0; k < KD; k += 16) {
        wmma::fragment<wmma::matrix_a, 16, 16, 16, __half, wmma::row_major> a;
        wmma::load_matrix_sync(a, ash + r0 * LDA + k, LDA);
#pragma unroll
        for (int nt = 0; nt < NOUT / 16; nt++) {
            wmma::fragment<wmma::matrix_b, 16, 16, 16, __half, wmma::row_major> b;
            wmma::load_matrix_sync(b, wsh + k * LDW + nt * 16, LDW);
            wmma::mma_sync(c[nt], a, b, c[nt]);
        }
    }

    __syncthreads();
    {
        float* tile = reinterpret_cast<float*>(ash) + warp * 16 * NOUT;  // 32KB total
#pragma unroll
        for (int nt = 0; nt < NOUT / 16; nt++)
            wmma::store_matrix_sync(tile + nt * 16, c[nt], NOUT, wmma::mem_row_major);
        __syncwarp();
#pragma unroll 4
        for (int r = 0; r < 16; r++) {
            int grow = rowB + r0 + r;
            if (grow < N) {
                float d = g_dinv[grow];
                float2 v = *reinterpret_cast<const float2*>(tile + r * NOUT + lane * 2);
                *reinterpret_cast<__half2*>(g_h2 + (size_t)grow * NOUT + lane * 2) =
                    __floats2half2_rn(v.x * d, v.y * d);
            }
        }
    }
}

// ---------------------------------------------------------------------------
// Atomic-free aggregation, one warp per destination node, fp16 messages.
// ---------------------------------------------------------------------------
template <int F, bool RELU, bool OUT_HALF>
__global__ void __launch_bounds__(256) agg_kernel(const float* __restrict__ bias,
                                                  float* __restrict__ OUT2, int N) {
    const __half* HS = (F == 128) ? g_h1 : g_h2;
    constexpr int V = F / 32;

    int col  = (blockIdx.x * blockDim.x + threadIdx.x) >> 5;
    int lane = threadIdx.x & 31;
    if (col >= N) return;

    const int   start = g_rowptr[col];
    const int   cnt   = g_cnt[col];
    const float d     = g_dinv[col];

    float v[V];
    {
        const __half* r = HS + (size_t)col * F + lane * V;
        if (V == 4) {
            half2x2 u = *reinterpret_cast<const half2x2*>(r);
            float2 f0 = __half22float2(u.a), f1 = __half22float2(u.b);
            v[0] = f0.x; v[1] = f0.y; v[2] = f1.x; v[3] = f1.y;
        } else {
            float2 f = __half22float2(*reinterpret_cast<const __half2*>(r));
            v[0] = f.x; v[1] = f.y;
        }
    }

    int j = 0;
    for (; j + 8 <= cnt; j += 8) {
        int si[8];
#pragma unroll
        for (int q = 0; q < 8; q++) si[q] = __ldg(&g_csr_src[start + j + q]);
        if (V == 4) {
            half2x2 u[8];
#pragma unroll
            for (int q = 0; q < 8; q++)
                u[q] = *reinterpret_cast<const half2x2*>(HS + (size_t)si[q] * F + lane * 4);
            float s0 = 0, s1 = 0, s2 = 0, s3 = 0;
#pragma unroll
            for (int q = 0; q < 8; q++) {
                float2 fa = __half22float2(u[q].a), fb = __half22float2(u[q].b);
                s0 += fa.x; s1 += fa.y; s2 += fb.x; s3 += fb.y;
            }
            v[0] += s0; v[1] += s1; v[2] += s2; v[3] += s3;
        } else {
            __half2 u[8];
#pragma unroll
            for (int q = 0; q < 8; q++)
                u[q] = *reinterpret_cast<const __half2*>(HS + (size_t)si[q] * F + lane * 2);
            float s0 = 0, s1 = 0;
#pragma unroll
            for (int q = 0; q < 8; q++) {
                float2 f = __half22float2(u[q]);
                s0 += f.x; s1 += f.y;
            }
            v[0] += s0; v[1] += s1;
        }
    }
    for (; j < cnt; j++) {
        int src = __ldg(&g_csr_src[start + j]);
        const __half* r = HS + (size_t)src * F + lane * V;
        if (V == 4) {
            half2x2 u = *reinterpret_cast<const half2x2*>(r);
            float2 f0 = __half22float2(u.a), f1 = __half22float2(u.b);
            v[0] += f0.x; v[1] += f0.y; v[2] += f1.x; v[3] += f1.y;
        } else {
            float2 f = __half22float2(*reinterpret_cast<const __half2*>(r));
            v[0] += f.x; v[1] += f.y;
        }
    }

#pragma unroll
    for (int q = 0; q < V; q++) {
        v[q] = fmaf(v[q], d, bias[lane * V + q]);
        if (RELU) v[q] = fmaxf(v[q], 0.0f);
    }

    if (OUT_HALF) {
        __half* o = g_acc1 + (size_t)col * F + lane * V;
        if (V == 4) {
            half2x2 p;
            p.a = __floats2half2_rn(v[0], v[1]);
            p.b = __floats2half2_rn(v[2], v[3]);
            *reinterpret_cast<half2x2*>(o) = p;
        } else {
            *reinterpret_cast<__half2*>(o) = __floats2half2_rn(v[0], v[1]);
        }
    } else {
        float* o = OUT2 + (size_t)col * F + lane * V;
        if (V == 4) {
            *reinterpret_cast<float4*>(o) = make_float4(v[0], v[1], v[2], v[3]);
        } else {
            *reinterpret_cast<float2*>(o) = make_float2(v[0], v[1]);
        }
    }
}

// ---------------------------------------------------------------------------
// Launch (10 kernels; gemm1 stays launch #4 -> profiled)
// ---------------------------------------------------------------------------
extern "C" void kernel_launch(void* const* d_in, const int* in_sizes, int n_in,
                              void* d_out, int out_size) {
    const float* x   = (const float*)d_in[0];
    const void*  ei  = d_in[1];
    const float* W1  = (const float*)d_in[4];
    const float* b1  = (const float*)d_in[5];
    const float* W2  = (const float*)d_in[6];
    const float* b2  = (const float*)d_in[7];
    float*       out = (float*)d_out;

    const int N   = in_sizes[0] / 128;
    const int E   = in_sizes[1] / 2;
    const int NB  = (N + 1023) / 1024;
    const int N4  = (N + 3) / 4;
    const int NX8 = (N * 128) / 8;

    setup_kernel<<<(NX8 + 255) / 256, 256>>>(x, (const int*)ei, N4, NX8);  // 1
    count_kernel<<<(E + 255) / 256, 256>>>(ei, E, N);                      // 2
    dinv_kernel<<<(N + 255) / 256, 256>>>(N);                              // 3
    gemm1_tc_kernel<<<(N + 127) / 128, 256>>>(W1, N);                      // 4 <- profiled
    scan_bsum_kernel<<<NB, 1024>>>(N);                                     // 5
    scan_local_kernel<<<NB, 1024>>>(N, NB);                                // 6
    fill_kernel<<<(E + 255) / 256, 256>>>(ei, E, N);                       // 7
    agg_kernel<128, true, true><<<(N * 32 + 255) / 256, 256>>>(b1, nullptr, N);  // 8
    gemm2_tc_kernel<<<(N + 127) / 128, 256>>>(W2, N);                      // 9
    agg_kernel<64, false, false><<<(N * 32 + 255) / 256, 256>>>(b2, out, N);     // 10
}

// round 13
// speedup vs baseline: 1.6962x; 1.1092x over previous
#include <cuda_runtime.h>
#include <cuda_fp16.h>
#include <mma.h>
#include <stdint.h>

using namespace nvcuda;

// Problem shape: N=50000 nodes, E=800000 edges, feature dims 128 -> 128 -> 64
#define MAXN 50176
#define MAXE 800000
#define MAXB ((MAXN + 1023) / 1024)

struct __align__(8) half2x2 { __half2 a, b; };

__device__ int g_is64;
__device__ __align__(16) int    g_cnt[MAXN];
__device__ __align__(16) int    g_fill[MAXN];
__device__ __align__(16) int    g_rowptr[MAXN];
__device__ __align__(16) int    g_bsum[MAXB];
__device__ __align__(16) int    g_csr_src[MAXE];
__device__ __align__(16) float  g_dinv[MAXN];
__device__ __align__(16) __half g_w1h[128 * 128];  // W1 fp16
__device__ __align__(16) __half g_w2h[128 * 64];   // W2 fp16
__device__ __align__(16) __half g_x16[MAXN * 128]; // x fp16
__device__ __align__(16) __half g_h1[MAXN * 128];  // (x @ W1) * dinv[row]
__device__ __align__(16) __half g_acc1[MAXN * 128];// relu(agg layer-1)
__device__ __align__(16) __half g_h2[MAXN * 64];   // (acc1 @ W2) * dinv[row]

__device__ __forceinline__ int edge_at(const void* ei, size_t idx) {
    return g_is64 ? (int)((const long long*)ei)[idx]
                  : ((const int*)ei)[idx];
}

__device__ __forceinline__ half2x2 cvt8(const float4 a, const float4 b) {
    half2x2 p;
    p.a = __floats2half2_rn(a.x, a.y); p.b = __floats2half2_rn(a.z, a.w);
    (void)b;
    return p;
}

// ---------------------------------------------------------------------------
// Setup: zero cnt/fill, convert x/W1/W2 -> fp16, detect edge dtype
// ---------------------------------------------------------------------------
__global__ void setup_kernel(const float* __restrict__ x,
                             const float* __restrict__ W1,
                             const float* __restrict__ W2,
                             const int* __restrict__ ei_w, int n4, int nx8) {
    int i = blockIdx.x * blockDim.x + threadIdx.x;
    if (i < n4) {
        reinterpret_cast<int4*>(g_cnt)[i]  = make_int4(0, 0, 0, 0);
        reinterpret_cast<int4*>(g_fill)[i] = make_int4(0, 0, 0, 0);
    }
    if (i < nx8) {
        float4 a = reinterpret_cast<const float4*>(x)[i * 2 + 0];
        float4 b = reinterpret_cast<const float4*>(x)[i * 2 + 1];
        half2x2 p0, p1;
        p0.a = __floats2half2_rn(a.x, a.y); p0.b = __floats2half2_rn(a.z, a.w);
        p1.a = __floats2half2_rn(b.x, b.y); p1.b = __floats2half2_rn(b.z, b.w);
        reinterpret_cast<half2x2*>(g_x16)[i * 2 + 0] = p0;
        reinterpret_cast<half2x2*>(g_x16)[i * 2 + 1] = p1;
    }
    if (i < 2048) {  // W1: 16384 halves = 2048 * 8
        float4 a = reinterpret_cast<const float4*>(W1)[i * 2 + 0];
        float4 b = reinterpret_cast<const float4*>(W1)[i * 2 + 1];
        half2x2 p0, p1;
        p0.a = __floats2half2_rn(a.x, a.y); p0.b = __floats2half2_rn(a.z, a.w);
        p1.a = __floats2half2_rn(b.x, b.y); p1.b = __floats2half2_rn(b.z, b.w);
        reinterpret_cast<half2x2*>(g_w1h)[i * 2 + 0] = p0;
        reinterpret_cast<half2x2*>(g_w1h)[i * 2 + 1] = p1;
    } else if (i < 3072) {  // W2: 8192 halves = 1024 * 8
        int j = i - 2048;
        float4 a = reinterpret_cast<const float4*>(W2)[j * 2 + 0];
        float4 b = reinterpret_cast<const float4*>(W2)[j * 2 + 1];
        half2x2 p0, p1;
        p0.a = __floats2half2_rn(a.x, a.y); p0.b = __floats2half2_rn(a.z, a.w);
        p1.a = __floats2half2_rn(b.x, b.y); p1.b = __floats2half2_rn(b.z, b.w);
        reinterpret_cast<half2x2*>(g_w2h)[j * 2 + 0] = p0;
        reinterpret_cast<half2x2*>(g_w2h)[j * 2 + 1] = p1;
    }
    if (blockIdx.x == 0 && threadIdx.x == 0) {
        int is64 = 1;
        for (int k = 1; k < 256; k += 2)
            if (ei_w[k] != 0) { is64 = 0; break; }
        g_is64 = is64;
    }
}

__global__ void count_kernel(const void* __restrict__ ei, int E, int N) {
    int e = blockIdx.x * blockDim.x + threadIdx.x;
    if (e < E) {
        int col = edge_at(ei, (size_t)E + e);
        if ((unsigned)col < (unsigned)N) atomicAdd(&g_cnt[col], 1);
    }
}

__global__ void dinv_kernel(int n) {
    int i = blockIdx.x * blockDim.x + threadIdx.x;
    if (i < n) g_dinv[i] = rsqrtf((float)(g_cnt[i] + 1));  // +1 self-loop
}

__global__ void __launch_bounds__(1024) scan_bsum_kernel(int N) {
    __shared__ int wsum[32];
    int b = blockIdx.x, t = threadIdx.x;
    int gid = b * 1024 + t;
    int v = (gid < N) ? g_cnt[gid] : 0;
    for (int o = 16; o > 0; o >>= 1) v += __shfl_down_sync(~0u, v, o);
    if ((t & 31) == 0) wsum[t >> 5] = v;
    __syncthreads();
    if (t < 32) {
        int s = wsum[t];
        for (int o = 16; o > 0; o >>= 1) s += __shfl_down_sync(~0u, s, o);
        if (t == 0) g_bsum[b] = s;
    }
}

__global__ void __launch_bounds__(1024) scan_local_kernel(int N, int NB) {
    __shared__ int wsum[32];
    __shared__ int boff_s[64];
    int b = blockIdx.x, t = threadIdx.x;

    if (t < 64) boff_s[t] = (t < NB) ? g_bsum[t] : 0;
    __syncthreads();
#pragma unroll
    for (int off = 1; off < 64; off <<= 1) {
        int v = (t < 64 && t >= off) ? boff_s[t - off] : 0;
        __syncthreads();
        if (t < 64) boff_s[t] += v;
        __syncthreads();
    }
    const int boff = (b > 0) ? boff_s[b - 1] : 0;

    int gid = b * 1024 + t;
    int lane = t & 31, w = t >> 5;
    int v = (gid < N) ? g_cnt[gid] : 0;
    int s = v;
    for (int o = 1; o < 32; o <<= 1) {
        int u = __shfl_up_sync(~0u, s, o);
        if (lane >= o) s += u;
    }
    if (lane == 31) wsum[w] = s;
    __syncthreads();
    if (t < 32) {
        int ws = wsum[t];
        for (int o = 1; o < 32; o <<= 1) {
            int u = __shfl_up_sync(~0u, ws, o);
            if (t >= o) ws += u;
        }
        wsum[t] = ws;
    }
    __syncthreads();
    int excl = s - v + ((w > 0) ? wsum[w - 1] : 0) + boff;
    if (gid < N) g_rowptr[gid] = excl;
}

__global__ void fill_kernel(const void* __restrict__ ei, int E, int N) {
    int e = blockIdx.x * blockDim.x + threadIdx.x;
    if (e < E) {
        int row = edge_at(ei, e);
        int col = edge_at(ei, (size_t)E + e);
        if ((unsigned)row < (unsigned)N && (unsigned)col < (unsigned)N) {
            int pos = g_rowptr[col] + atomicAdd(&g_fill[col], 1);
            g_csr_src[pos] = row;
        }
    }
}

// ---------------------------------------------------------------------------
// Layer-1 GEMM (fp16 wmma m16n16k16): h1 = half((x16 @ W1) * dinv[row])
// 64 rows/block, 256 threads. Warp w: rows (w&3)*16, cols (w>>2)*64.
// smem 52KB -> 4 blocks/SM (50% occ). W pre-converted fp16 (uint4 copies).
// ---------------------------------------------------------------------------
__global__ void __launch_bounds__(256) gemm1_tc_kernel(int N) {
    constexpr int KD = 128, NOUT = 128, LDW = 136, ROWS = 64;
    __shared__ __align__(16) __half wsh[KD * LDW];    // 34816 B
    __shared__ __align__(16) __half ash[ROWS * LDW];  // 17408 B

    const int warp = threadIdx.x >> 5;
    const int lane = threadIdx.x & 31;
    const int rowB = blockIdx.x * ROWS;

    // Stage W: 2048 uint4 copies (8 per thread)
#pragma unroll
    for (int i = threadIdx.x; i < KD * (NOUT / 8); i += 256) {
        int k = i >> 4, c = (i & 15) * 8;
        *reinterpret_cast<uint4*>(&wsh[k * LDW + c]) =
            reinterpret_cast<const uint4*>(g_w1h)[i];
    }
    // Stage A: 1024 uint4 (4 per thread), zero-fill rows >= N
#pragma unroll
    for (int i = threadIdx.x; i < ROWS * (KD / 8); i += 256) {
        int r = i >> 4, c = (i & 15) * 8;
        uint4 u = (rowB + r < N)
            ? *reinterpret_cast<const uint4*>(g_x16 + (size_t)(rowB + r) * KD + c)
            : make_uint4(0, 0, 0, 0);
        *reinterpret_cast<uint4*>(&ash[r * LDW + c]) = u;
    }
    __syncthreads();

    const int r0 = (warp & 3) * 16;
    const int n0 = (warp >> 2) * 64;

    wmma::fragment<wmma::accumulator, 16, 16, 16, float> c[4];
#pragma unroll
    for (int i = 0; i < 4; i++) wmma::fill_fragment(c[i], 0.0f);

#pragma unroll
    for (int k = 0; k < KD; k += 16) {
        wmma::fragment<wmma::matrix_a, 16, 16, 16, __half, wmma::row_major> a;
        wmma::load_matrix_sync(a, ash + r0 * LDW + k, LDW);
#pragma unroll
        for (int nt = 0; nt < 4; nt++) {
            wmma::fragment<wmma::matrix_b, 16, 16, 16, __half, wmma::row_major> b;
            wmma::load_matrix_sync(b, wsh + k * LDW + n0 + nt * 16, LDW);
            wmma::mma_sync(c[nt], a, b, c[nt]);
        }
    }

    __syncthreads();  // wsh free; reuse as fp32 epilogue tile (8 x 4KB = 32KB)
    {
        float* tile = reinterpret_cast<float*>(wsh) + warp * (16 * 64);
#pragma unroll
        for (int nt = 0; nt < 4; nt++)
            wmma::store_matrix_sync(tile + nt * 16, c[nt], 64, wmma::mem_row_major);
        __syncwarp();
#pragma unroll 4
        for (int r = 0; r < 16; r++) {
            int grow = rowB + r0 + r;
            if (grow < N) {
                float d = g_dinv[grow];
                float2 v = *reinterpret_cast<const float2*>(tile + r * 64 + lane * 2);
                *reinterpret_cast<__half2*>(g_h1 + (size_t)grow * NOUT + n0 + lane * 2) =
                    __floats2half2_rn(v.x * d, v.y * d);
            }
        }
    }
}

// ---------------------------------------------------------------------------
// Layer-2 GEMM (fp16 wmma m16n16k16): h2 = half((acc1 @ W2) * dinv[row])
// 128 rows/block, warp owns 16 rows x 64 cols. W pre-converted fp16.
// ---------------------------------------------------------------------------
__global__ void __launch_bounds__(256) gemm2_tc_kernel(int N) {
    constexpr int KD = 128, NOUT = 64, LDW = 72, LDA = 136, ROWS = 128;
    __shared__ __align__(16) __half wsh[KD * LDW];    // 18432 B
    __shared__ __align__(16) __half ash[ROWS * LDA];  // 34816 B

    const int warp = threadIdx.x >> 5;
    const int lane = threadIdx.x & 31;
    const int rowB = blockIdx.x * ROWS;

#pragma unroll
    for (int i = threadIdx.x; i < KD * (NOUT / 8); i += 256) {
        int k = i >> 3, c = (i & 7) * 8;
        *reinterpret_cast<uint4*>(&wsh[k * LDW + c]) =
            reinterpret_cast<const uint4*>(g_w2h)[i];
    }
#pragma unroll
    for (int i = threadIdx.x; i < ROWS * (KD / 8); i += 256) {
        int r = i >> 4, c = (i & 15) * 8;
        uint4 u = (rowB + r < N)
            ? *reinterpret_cast<const uint4*>(g_acc1 + (size_t)(rowB + r) * KD + c)
            : make_uint4(0, 0, 0, 0);
        *reinterpret_cast<uint4*>(&ash[r * LDA + c]) = u;
    }
    __syncthreads();

    const int r0 = warp * 16;

    wmma::fragment<wmma::accumulator, 16, 16, 16, float> c[4];
#pragma unroll
    for (int i = 0; i < 4; i++) wmma::fill_fragment(c[i], 0.0f);

#pragma unroll
    for (int k = 0; k < KD; k += 16) {
        wmma::fragment<wmma::matrix_a, 16, 16, 16, __half, wmma::row_major> a;
        wmma::load_matrix_sync(a, ash + r0 * LDA + k, LDA);
#pragma unroll
        for (int nt = 0; nt < 4; nt++) {
            wmma::fragment<wmma::matrix_b, 16, 16, 16, __half, wmma::row_major> b;
            wmma::load_matrix_sync(b, wsh + k * LDW + nt * 16, LDW);
            wmma::mma_sync(c[nt], a, b, c[nt]);
        }
    }

    __syncthreads();
    {
        float* tile = reinterpret_cast<float*>(ash) + warp * (16 * 64);  // 32KB
#pragma unroll
        for (int nt = 0; nt < 4; nt++)
            wmma::store_matrix_sync(tile + nt * 16, c[nt], 64, wmma::mem_row_major);
        __syncwarp();
#pragma unroll 4
        for (int r = 0; r < 16; r++) {
            int grow = rowB + r0 + r;
            if (grow < N) {
                float d = g_dinv[grow];
                float2 v = *reinterpret_cast<const float2*>(tile + r * 64 + lane * 2);
                *reinterpret_cast<__half2*>(g_h2 + (size_t)grow * NOUT + lane * 2) =
                    __floats2half2_rn(v.x * d, v.y * d);
            }
        }
    }
}

// ---------------------------------------------------------------------------
// Atomic-free aggregation, one warp per destination node, fp16 messages.
// ---------------------------------------------------------------------------
template <int F, bool RELU, bool OUT_HALF>
__global__ void __launch_bounds__(256) agg_kernel(const float* __restrict__ bias,
                                                  float* __restrict__ OUT2, int N) {
    const __half* HS = (F == 128) ? g_h1 : g_h2;
    constexpr int V = F / 32;

    int col  = (blockIdx.x * blockDim.x + threadIdx.x) >> 5;
    int lane = threadIdx.x & 31;
    if (col >= N) return;

    const int   start = g_rowptr[col];
    const int   cnt   = g_cnt[col];
    const float d     = g_dinv[col];

    float v[V];
    {
        const __half* r = HS + (size_t)col * F + lane * V;
        if (V == 4) {
            half2x2 u = *reinterpret_cast<const half2x2*>(r);
            float2 f0 = __half22float2(u.a), f1 = __half22float2(u.b);
            v[0] = f0.x; v[1] = f0.y; v[2] = f1.x; v[3] = f1.y;
        } else {
            float2 f = __half22float2(*reinterpret_cast<const __half2*>(r));
            v[0] = f.x; v[1] = f.y;
        }
    }

    int j = 0;
    for (; j + 8 <= cnt; j += 8) {
        int si[8];
#pragma unroll
        for (int q = 0; q < 8; q++) si[q] = __ldg(&g_csr_src[start + j + q]);
        if (V == 4) {
            half2x2 u[8];
#pragma unroll
            for (int q = 0; q < 8; q++)
                u[q] = *reinterpret_cast<const half2x2*>(HS + (size_t)si[q] * F + lane * 4);
            float s0 = 0, s1 = 0, s2 = 0, s3 = 0;
#pragma unroll
            for (int q = 0; q < 8; q++) {
                float2 fa = __half22float2(u[q].a), fb = __half22float2(u[q].b);
                s0 += fa.x; s1 += fa.y; s2 += fb.x; s3 += fb.y;
            }
            v[0] += s0; v[1] += s1; v[2] += s2; v[3] += s3;
        } else {
            __half2 u[8];
#pragma unroll
            for (int q = 0; q < 8; q++)
                u[q] = *reinterpret_cast<const __half2*>(HS + (size_t)si[q] * F + lane * 2);
            float s0 = 0, s1 = 0;
#pragma unroll
            for (int q = 0; q < 8; q++) {
                float2 f = __half22float2(u[q]);
                s0 += f.x; s1 += f.y;
            }
            v[0] += s0; v[1] += s1;
        }
    }
    for (; j < cnt; j++) {
        int src = __ldg(&g_csr_src[start + j]);
        const __half* r = HS + (size_t)src * F + lane * V;
        if (V == 4) {
            half2x2 u = *reinterpret_cast<const half2x2*>(r);
            float2 f0 = __half22float2(u.a), f1 = __half22float2(u.b);
            v[0] += f0.x; v[1] += f0.y; v[2] += f1.x; v[3] += f1.y;
        } else {
            float2 f = __half22float2(*reinterpret_cast<const __half2*>(r));
            v[0] += f.x; v[1] += f.y;
        }
    }

#pragma unroll
    for (int q = 0; q < V; q++) {
        v[q] = fmaf(v[q], d, bias[lane * V + q]);
        if (RELU) v[q] = fmaxf(v[q], 0.0f);
    }

    if (OUT_HALF) {
        __half* o = g_acc1 + (size_t)col * F + lane * V;
        if (V == 4) {
            half2x2 p;
            p.a = __floats2half2_rn(v[0], v[1]);
            p.b = __floats2half2_rn(v[2], v[3]);
            *reinterpret_cast<half2x2*>(o) = p;
        } else {
            *reinterpret_cast<__half2*>(o) = __floats2half2_rn(v[0], v[1]);
        }
    } else {
        float* o = OUT2 + (size_t)col * F + lane * V;
        if (V == 4) {
            *reinterpret_cast<float4*>(o) = make_float4(v[0], v[1], v[2], v[3]);
        } else {
            *reinterpret_cast<float2*>(o) = make_float2(v[0], v[1]);
        }
    }
}

// ---------------------------------------------------------------------------
// Launch (10 kernels; gemm1 stays launch #4 -> profiled)
// ---------------------------------------------------------------------------
extern "C" void kernel_launch(void* const* d_in, const int* in_sizes, int n_in,
                              void* d_out, int out_size) {
    const float* x   = (const float*)d_in[0];
    const void*  ei  = d_in[1];
    const float* W1  = (const float*)d_in[4];
    const float* b1  = (const float*)d_in[5];
    const float* W2  = (const float*)d_in[6];
    const float* b2  = (const float*)d_in[7];
    float*       out = (float*)d_out;

    const int N   = in_sizes[0] / 128;
    const int E   = in_sizes[1] / 2;
    const int NB  = (N + 1023) / 1024;
    const int N4  = (N + 3) / 4;
    const int NX8 = (N * 128) / 8;

    setup_kernel<<<(NX8 + 255) / 256, 256>>>(x, W1, W2, (const int*)ei, N4, NX8); // 1
    count_kernel<<<(E + 255) / 256, 256>>>(ei, E, N);                             // 2
    dinv_kernel<<<(N + 255) / 256, 256>>>(N);                                     // 3
    gemm1_tc_kernel<<<(N + 63) / 64, 256>>>(N);                                   // 4 <- profiled
    scan_bsum_kernel<<<NB, 1024>>>(N);                                            // 5
    scan_local_kernel<<<NB, 1024>>>(N, NB);                                       // 6
    fill_kernel<<<(E + 255) / 256, 256>>>(ei, E, N);                              // 7
    agg_kernel<128, true, true><<<(N * 32 + 255) / 256, 256>>>(b1, nullptr, N);   // 8
    gemm2_tc_kernel<<<(N + 127) / 128, 256>>>(N);                                 // 9
    agg_kernel<64, false, false><<<(N * 32 + 255) / 256, 256>>>(b2, out, N);      // 10
}

// round 14
// speedup vs baseline: 1.7013x; 1.0030x over previous
#include <cuda_runtime.h>
#include <cuda_fp16.h>
#include <mma.h>
#include <stdint.h>

using namespace nvcuda;

// Problem shape: N=50000 nodes, E=800000 edges, feature dims 128 -> 128 -> 64
#define MAXN 50176
#define MAXE 800000
#define MAXB ((MAXN + 1023) / 1024)

struct __align__(8) half2x2 { __half2 a, b; };

__device__ int g_is64;
__device__ __align__(16) int    g_cnt[MAXN];
__device__ __align__(16) int    g_fill[MAXN];
__device__ __align__(16) int    g_rowptr[MAXN];
__device__ __align__(16) int    g_bsum[MAXB];
__device__ __align__(16) int    g_csr_src[MAXE];
__device__ __align__(16) float  g_dinv[MAXN];
__device__ __align__(16) __half g_w1h[128 * 128];  // W1 fp16
__device__ __align__(16) __half g_w2h[128 * 64];   // W2 fp16
__device__ __align__(16) __half g_x16[MAXN * 128]; // x fp16
__device__ __align__(16) __half g_h1[MAXN * 128];  // x @ W1 (UNscaled)
__device__ __align__(16) __half g_acc1[MAXN * 128];// relu(agg layer-1)
__device__ __align__(16) __half g_h2[MAXN * 64];   // acc1 @ W2 (UNscaled)

__device__ __forceinline__ int edge_at(const void* ei, size_t idx) {
    return g_is64 ? (int)((const long long*)ei)[idx]
                  : ((const int*)ei)[idx];
}

// ---------------------------------------------------------------------------
// Setup: zero cnt/fill, convert x/W1/W2 -> fp16, detect edge dtype
// ---------------------------------------------------------------------------
__global__ void setup_kernel(const float* __restrict__ x,
                             const float* __restrict__ W1,
                             const float* __restrict__ W2,
                             const int* __restrict__ ei_w, int n4, int nx8) {
    int i = blockIdx.x * blockDim.x + threadIdx.x;
    if (i < n4) {
        reinterpret_cast<int4*>(g_cnt)[i]  = make_int4(0, 0, 0, 0);
        reinterpret_cast<int4*>(g_fill)[i] = make_int4(0, 0, 0, 0);
    }
    if (i < nx8) {
        float4 a = reinterpret_cast<const float4*>(x)[i * 2 + 0];
        float4 b = reinterpret_cast<const float4*>(x)[i * 2 + 1];
        half2x2 p0, p1;
        p0.a = __floats2half2_rn(a.x, a.y); p0.b = __floats2half2_rn(a.z, a.w);
        p1.a = __floats2half2_rn(b.x, b.y); p1.b = __floats2half2_rn(b.z, b.w);
        reinterpret_cast<half2x2*>(g_x16)[i * 2 + 0] = p0;
        reinterpret_cast<half2x2*>(g_x16)[i * 2 + 1] = p1;
    }
    if (i < 2048) {  // W1: 16384 halves
        float4 a = reinterpret_cast<const float4*>(W1)[i * 2 + 0];
        float4 b = reinterpret_cast<const float4*>(W1)[i * 2 + 1];
        half2x2 p0, p1;
        p0.a = __floats2half2_rn(a.x, a.y); p0.b = __floats2half2_rn(a.z, a.w);
        p1.a = __floats2half2_rn(b.x, b.y); p1.b = __floats2half2_rn(b.z, b.w);
        reinterpret_cast<half2x2*>(g_w1h)[i * 2 + 0] = p0;
        reinterpret_cast<half2x2*>(g_w1h)[i * 2 + 1] = p1;
    } else if (i < 3072) {  // W2: 8192 halves
        int j = i - 2048;
        float4 a = reinterpret_cast<const float4*>(W2)[j * 2 + 0];
        float4 b = reinterpret_cast<const float4*>(W2)[j * 2 + 1];
        half2x2 p0, p1;
        p0.a = __floats2half2_rn(a.x, a.y); p0.b = __floats2half2_rn(a.z, a.w);
        p1.a = __floats2half2_rn(b.x, b.y); p1.b = __floats2half2_rn(b.z, b.w);
        reinterpret_cast<half2x2*>(g_w2h)[j * 2 + 0] = p0;
        reinterpret_cast<half2x2*>(g_w2h)[j * 2 + 1] = p1;
    }
    if (blockIdx.x == 0 && threadIdx.x == 0) {
        int is64 = 1;
        for (int k = 1; k < 256; k += 2)
            if (ei_w[k] != 0) { is64 = 0; break; }
        g_is64 = is64;
    }
}

__global__ void count_kernel(const void* __restrict__ ei, int E, int N) {
    int e = blockIdx.x * blockDim.x + threadIdx.x;
    if (e < E) {
        int col = edge_at(ei, (size_t)E + e);
        if ((unsigned)col < (unsigned)N) atomicAdd(&g_cnt[col], 1);
    }
}

// block sums for scan + fused dinv computation
__global__ void __launch_bounds__(1024) scan_bsum_kernel(int N) {
    __shared__ int wsum[32];
    int b = blockIdx.x, t = threadIdx.x;
    int gid = b * 1024 + t;
    int v = (gid < N) ? g_cnt[gid] : 0;
    if (gid < N) g_dinv[gid] = rsqrtf((float)(v + 1));  // +1 self-loop
    int s = v;
    for (int o = 16; o > 0; o >>= 1) s += __shfl_down_sync(~0u, s, o);
    if ((t & 31) == 0) wsum[t >> 5] = s;
    __syncthreads();
    if (t < 32) {
        int w = wsum[t];
        for (int o = 16; o > 0; o >>= 1) w += __shfl_down_sync(~0u, w, o);
        if (t == 0) g_bsum[b] = w;
    }
}

__global__ void __launch_bounds__(1024) scan_local_kernel(int N, int NB) {
    __shared__ int wsum[32];
    __shared__ int boff_s[64];
    int b = blockIdx.x, t = threadIdx.x;

    if (t < 64) boff_s[t] = (t < NB) ? g_bsum[t] : 0;
    __syncthreads();
#pragma unroll
    for (int off = 1; off < 64; off <<= 1) {
        int v = (t < 64 && t >= off) ? boff_s[t - off] : 0;
        __syncthreads();
        if (t < 64) boff_s[t] += v;
        __syncthreads();
    }
    const int boff = (b > 0) ? boff_s[b - 1] : 0;

    int gid = b * 1024 + t;
    int lane = t & 31, w = t >> 5;
    int v = (gid < N) ? g_cnt[gid] : 0;
    int s = v;
    for (int o = 1; o < 32; o <<= 1) {
        int u = __shfl_up_sync(~0u, s, o);
        if (lane >= o) s += u;
    }
    if (lane == 31) wsum[w] = s;
    __syncthreads();
    if (t < 32) {
        int ws = wsum[t];
        for (int o = 1; o < 32; o <<= 1) {
            int u = __shfl_up_sync(~0u, ws, o);
            if (t >= o) ws += u;
        }
        wsum[t] = ws;
    }
    __syncthreads();
    int excl = s - v + ((w > 0) ? wsum[w - 1] : 0) + boff;
    if (gid < N) g_rowptr[gid] = excl;
}

__global__ void fill_kernel(const void* __restrict__ ei, int E, int N) {
    int e = blockIdx.x * blockDim.x + threadIdx.x;
    if (e < E) {
        int row = edge_at(ei, e);
        int col = edge_at(ei, (size_t)E + e);
        if ((unsigned)row < (unsigned)N && (unsigned)col < (unsigned)N) {
            int pos = g_rowptr[col] + atomicAdd(&g_fill[col], 1);
            g_csr_src[pos] = row;
        }
    }
}

// ---------------------------------------------------------------------------
// Layer-1 GEMM (fp16 wmma m16n16k16): h1 = half(x16 @ W1)   (UNscaled)
// 64 rows/block, 256 threads; warp w: rows (w&3)*16, cols (w>>2)*64.
// Depends ONLY on setup -> runs on the side stream, overlapped with CSR build.
// ---------------------------------------------------------------------------
__global__ void __launch_bounds__(256) gemm1_tc_kernel(int N) {
    constexpr int KD = 128, NOUT = 128, LDW = 136, ROWS = 64;
    __shared__ __align__(16) __half wsh[KD * LDW];    // 34816 B
    __shared__ __align__(16) __half ash[ROWS * LDW];  // 17408 B

    const int warp = threadIdx.x >> 5;
    const int lane = threadIdx.x & 31;
    const int rowB = blockIdx.x * ROWS;

#pragma unroll
    for (int i = threadIdx.x; i < KD * (NOUT / 8); i += 256) {
        int k = i >> 4, c = (i & 15) * 8;
        *reinterpret_cast<uint4*>(&wsh[k * LDW + c]) =
            reinterpret_cast<const uint4*>(g_w1h)[i];
    }
#pragma unroll
    for (int i = threadIdx.x; i < ROWS * (KD / 8); i += 256) {
        int r = i >> 4, c = (i & 15) * 8;
        uint4 u = (rowB + r < N)
            ? *reinterpret_cast<const uint4*>(g_x16 + (size_t)(rowB + r) * KD + c)
            : make_uint4(0, 0, 0, 0);
        *reinterpret_cast<uint4*>(&ash[r * LDW + c]) = u;
    }
    __syncthreads();

    const int r0 = (warp & 3) * 16;
    const int n0 = (warp >> 2) * 64;

    wmma::fragment<wmma::accumulator, 16, 16, 16, float> c[4];
#pragma unroll
    for (int i = 0; i < 4; i++) wmma::fill_fragment(c[i], 0.0f);

#pragma unroll
    for (int k = 0; k < KD; k += 16) {
        wmma::fragment<wmma::matrix_a, 16, 16, 16, __half, wmma::row_major> a;
        wmma::load_matrix_sync(a, ash + r0 * LDW + k, LDW);
#pragma unroll
        for (int nt = 0; nt < 4; nt++) {
            wmma::fragment<wmma::matrix_b, 16, 16, 16, __half, wmma::row_major> b;
            wmma::load_matrix_sync(b, wsh + k * LDW + n0 + nt * 16, LDW);
            wmma::mma_sync(c[nt], a, b, c[nt]);
        }
    }

    __syncthreads();
    {
        float* tile = reinterpret_cast<float*>(wsh) + warp * (16 * 64);
#pragma unroll
        for (int nt = 0; nt < 4; nt++)
            wmma::store_matrix_sync(tile + nt * 16, c[nt], 64, wmma::mem_row_major);
        __syncwarp();
#pragma unroll 4
        for (int r = 0; r < 16; r++) {
            int grow = rowB + r0 + r;
            if (grow < N) {
                float2 v = *reinterpret_cast<const float2*>(tile + r * 64 + lane * 2);
                *reinterpret_cast<__half2*>(g_h1 + (size_t)grow * NOUT + n0 + lane * 2) =
                    __floats2half2_rn(v.x, v.y);
            }
        }
    }
}

// ---------------------------------------------------------------------------
// Layer-2 GEMM (fp16 wmma m16n16k16): h2 = half(acc1 @ W2)  (UNscaled)
// ---------------------------------------------------------------------------
__global__ void __launch_bounds__(256) gemm2_tc_kernel(int N) {
    constexpr int KD = 128, NOUT = 64, LDW = 72, LDA = 136, ROWS = 128;
    __shared__ __align__(16) __half wsh[KD * LDW];    // 18432 B
    __shared__ __align__(16) __half ash[ROWS * LDA];  // 34816 B

    const int warp = threadIdx.x >> 5;
    const int lane = threadIdx.x & 31;
    const int rowB = blockIdx.x * ROWS;

#pragma unroll
    for (int i = threadIdx.x; i < KD * (NOUT / 8); i += 256) {
        int k = i >> 3, c = (i & 7) * 8;
        *reinterpret_cast<uint4*>(&wsh[k * LDW + c]) =
            reinterpret_cast<const uint4*>(g_w2h)[i];
    }
#pragma unroll
    for (int i = threadIdx.x; i < ROWS * (KD / 8); i += 256) {
        int r = i >> 4, c = (i & 15) * 8;
        uint4 u = (rowB + r < N)
            ? *reinterpret_cast<const uint4*>(g_acc1 + (size_t)(rowB + r) * KD + c)
            : make_uint4(0, 0, 0, 0);
        *reinterpret_cast<uint4*>(&ash[r * LDA + c]) = u;
    }
    __syncthreads();

    const int r0 = warp * 16;

    wmma::fragment<wmma::accumulator, 16, 16, 16, float> c[4];
#pragma unroll
    for (int i = 0; i < 4; i++) wmma::fill_fragment(c[i], 0.0f);

#pragma unroll
    for (int k = 0; k < KD; k += 16) {
        wmma::fragment<wmma::matrix_a, 16, 16, 16, __half, wmma::row_major> a;
        wmma::load_matrix_sync(a, ash + r0 * LDA + k, LDA);
#pragma unroll
        for (int nt = 0; nt < 4; nt++) {
            wmma::fragment<wmma::matrix_b, 16, 16, 16, __half, wmma::row_major> b;
            wmma::load_matrix_sync(b, wsh + k * LDW + nt * 16, LDW);
            wmma::mma_sync(c[nt], a, b, c[nt]);
        }
    }

    __syncthreads();
    {
        float* tile = reinterpret_cast<float*>(ash) + warp * (16 * 64);
#pragma unroll
        for (int nt = 0; nt < 4; nt++)
            wmma::store_matrix_sync(tile + nt * 16, c[nt], 64, wmma::mem_row_major);
        __syncwarp();
#pragma unroll 4
        for (int r = 0; r < 16; r++) {
            int grow = rowB + r0 + r;
            if (grow < N) {
                float2 v = *reinterpret_cast<const float2*>(tile + r * 64 + lane * 2);
                *reinterpret_cast<__half2*>(g_h2 + (size_t)grow * NOUT + lane * 2) =
                    __floats2half2_rn(v.x, v.y);
            }
        }
    }
}

// ---------------------------------------------------------------------------
// Atomic-free aggregation, one warp per destination node, fp16 messages,
// per-edge dinv[src] scaling (h is unscaled now):
//   out[col] = (relu?)( d * ( h[col]*d + sum h[src]*dinv[src] ) + bias )
// ---------------------------------------------------------------------------
template <int F, bool RELU, bool OUT_HALF>
__global__ void __launch_bounds__(256) agg_kernel(const float* __restrict__ bias,
                                                  float* __restrict__ OUT2, int N) {
    const __half* HS = (F == 128) ? g_h1 : g_h2;
    constexpr int V = F / 32;

    int col  = (blockIdx.x * blockDim.x + threadIdx.x) >> 5;
    int lane = threadIdx.x & 31;
    if (col >= N) return;

    const int   start = g_rowptr[col];
    const int   cnt   = g_cnt[col];
    const float d     = g_dinv[col];

    float v[V];
    {   // self-loop term: h[col] * dinv[col]
        const __half* r = HS + (size_t)col * F + lane * V;
        if (V == 4) {
            half2x2 u = *reinterpret_cast<const half2x2*>(r);
            float2 f0 = __half22float2(u.a), f1 = __half22float2(u.b);
            v[0] = f0.x * d; v[1] = f0.y * d; v[2] = f1.x * d; v[3] = f1.y * d;
        } else {
            float2 f = __half22float2(*reinterpret_cast<const __half2*>(r));
            v[0] = f.x * d; v[1] = f.y * d;
        }
    }

    int j = 0;
    for (; j + 8 <= cnt; j += 8) {
        int si[8];
        float ds[8];
#pragma unroll
        for (int q = 0; q < 8; q++) si[q] = __ldg(&g_csr_src[start + j + q]);
#pragma unroll
        for (int q = 0; q < 8; q++) ds[q] = __ldg(&g_dinv[si[q]]);
        if (V == 4) {
            half2x2 u[8];
#pragma unroll
            for (int q = 0; q < 8; q++)
                u[q] = *reinterpret_cast<const half2x2*>(HS + (size_t)si[q] * F + lane * 4);
#pragma unroll
            for (int q = 0; q < 8; q++) {
                float2 fa = __half22float2(u[q].a), fb = __half22float2(u[q].b);
                v[0] = fmaf(fa.x, ds[q], v[0]);
                v[1] = fmaf(fa.y, ds[q], v[1]);
                v[2] = fmaf(fb.x, ds[q], v[2]);
                v[3] = fmaf(fb.y, ds[q], v[3]);
            }
        } else {
            __half2 u[8];
#pragma unroll
            for (int q = 0; q < 8; q++)
                u[q] = *reinterpret_cast<const __half2*>(HS + (size_t)si[q] * F + lane * 2);
#pragma unroll
            for (int q = 0; q < 8; q++) {
                float2 f = __half22float2(u[q]);
                v[0] = fmaf(f.x, ds[q], v[0]);
                v[1] = fmaf(f.y, ds[q], v[1]);
            }
        }
    }
    for (; j < cnt; j++) {
        int src = __ldg(&g_csr_src[start + j]);
        float ds = __ldg(&g_dinv[src]);
        const __half* r = HS + (size_t)src * F + lane * V;
        if (V == 4) {
            half2x2 u = *reinterpret_cast<const half2x2*>(r);
            float2 f0 = __half22float2(u.a), f1 = __half22float2(u.b);
            v[0] = fmaf(f0.x, ds, v[0]); v[1] = fmaf(f0.y, ds, v[1]);
            v[2] = fmaf(f1.x, ds, v[2]); v[3] = fmaf(f1.y, ds, v[3]);
        } else {
            float2 f = __half22float2(*reinterpret_cast<const __half2*>(r));
            v[0] = fmaf(f.x, ds, v[0]); v[1] = fmaf(f.y, ds, v[1]);
        }
    }

#pragma unroll
    for (int q = 0; q < V; q++) {
        v[q] = fmaf(v[q], d, bias[lane * V + q]);
        if (RELU) v[q] = fmaxf(v[q], 0.0f);
    }

    if (OUT_HALF) {
        __half* o = g_acc1 + (size_t)col * F + lane * V;
        if (V == 4) {
            half2x2 p;
            p.a = __floats2half2_rn(v[0], v[1]);
            p.b = __floats2half2_rn(v[2], v[3]);
            *reinterpret_cast<half2x2*>(o) = p;
        } else {
            *reinterpret_cast<__half2*>(o) = __floats2half2_rn(v[0], v[1]);
        }
    } else {
        float* o = OUT2 + (size_t)col * F + lane * V;
        if (V == 4) {
            *reinterpret_cast<float4*>(o) = make_float4(v[0], v[1], v[2], v[3]);
        } else {
            *reinterpret_cast<float2*>(o) = make_float2(v[0], v[1]);
        }
    }
}

// ---------------------------------------------------------------------------
// Launch: gemm1 forked onto a side stream, overlapped with the CSR build.
// Stream/event creation is host-side (not captured, no device allocation);
// record/wait are graph-capturable fork/join nodes.
// ---------------------------------------------------------------------------
extern "C" void kernel_launch(void* const* d_in, const int* in_sizes, int n_in,
                              void* d_out, int out_size) {
    const float* x   = (const float*)d_in[0];
    const void*  ei  = d_in[1];
    const float* W1  = (const float*)d_in[4];
    const float* b1  = (const float*)d_in[5];
    const float* W2  = (const float*)d_in[6];
    const float* b2  = (const float*)d_in[7];
    float*       out = (float*)d_out;

    const int N   = in_sizes[0] / 128;
    const int E   = in_sizes[1] / 2;
    const int NB  = (N + 1023) / 1024;
    const int N4  = (N + 3) / 4;
    const int NX8 = (N * 128) / 8;

    cudaStream_t s1;
    cudaEvent_t eSetup, eG1;
    cudaStreamCreateWithFlags(&s1, cudaStreamNonBlocking);
    cudaEventCreateWithFlags(&eSetup, cudaEventDisableTiming);
    cudaEventCreateWithFlags(&eG1, cudaEventDisableTiming);

    // main stream (0): setup, then CSR build
    setup_kernel<<<(NX8 + 255) / 256, 256>>>(x, W1, W2, (const int*)ei, N4, NX8);
    cudaEventRecord(eSetup, 0);

    // side stream: gemm1 (needs only setup's outputs)
    cudaStreamWaitEvent(s1, eSetup, 0);
    gemm1_tc_kernel<<<(N + 63) / 64, 256, 0, s1>>>(N);
    cudaEventRecord(eG1, s1);

    // main stream: CSR build chain (overlapped with gemm1)
    count_kernel<<<(E + 255) / 256, 256>>>(ei, E, N);
    scan_bsum_kernel<<<NB, 1024>>>(N);      // + dinv fused
    scan_local_kernel<<<NB, 1024>>>(N, NB);
    fill_kernel<<<(E + 255) / 256, 256>>>(ei, E, N);

    // join: aggregation needs both gemm1 and the CSR build
    cudaStreamWaitEvent(0, eG1, 0);
    agg_kernel<128, true, true><<<(N * 32 + 255) / 256, 256>>>(b1, nullptr, N);
    gemm2_tc_kernel<<<(N + 127) / 128, 256>>>(N);
    agg_kernel<64, false, false><<<(N * 32 + 255) / 256, 256>>>(b2, out, N);
    // (stream/events intentionally not destroyed: capture may still reference them)
}